// round 1
// baseline (speedup 1.0000x reference)
#include <cuda_runtime.h>
#include <math.h>

#define MM 8
#define NN 8192
#define KK 256
#define NUM_ITERS 6
#define FIX_ITER 1

#define LOG2E 1.44269504088896340736f
#define EPS_C 0.01f
#define GAMMA_C 0.005f

#define BPM 37            // blocks per shape m (8*37 = 296 blocks = 2/SM)
#define WPM (BPM * 8)     // warps per shape

static __device__ __forceinline__ float ex2f(float x) {
    float y; asm("ex2.approx.f32 %0, %1;" : "=f"(y) : "f"(x)); return y;
}
static __device__ __forceinline__ float rcpf(float x) {
    float y; asm("rcp.approx.f32 %0, %1;" : "=f"(y) : "f"(x)); return y;
}

// ------------- persistent device state (no allocations allowed) -------------
__device__ float gL[MM][KK], gWx[MM][KK], gWy[MM][KK], gWz[MM][KK], gS2[MM][KK];
__device__ float gR[MM][9];     // row-major R[a][b]
__device__ float gT[MM][3];
__device__ float gX[KK][3];
__device__ float gQ[KK];
__device__ float gC0[KK], gC1[KK], gDx[KK], gDy[KK], gDz[KK];
__device__ float gBeta;

// ------------------------------- init ---------------------------------------
__global__ void init_kernel(const float* __restrict__ Vs,
                            const float* __restrict__ X0,
                            const float* __restrict__ Q0) {
    int tid = threadIdx.x;
    int lane = tid & 31, warp = tid >> 5;

    // t0[m][d] = -mean_n Vs[m,d,n]; 24 (m,d) pairs across 8 warps
    for (int p = warp; p < 24; p += 8) {
        int m = p / 3, d = p % 3;
        const float* src = Vs + (m * 3 + d) * NN;
        float s = 0.f;
        for (int n = lane; n < NN; n += 32) s += src[n];
        #pragma unroll
        for (int o = 16; o; o >>= 1) s += __shfl_xor_sync(0xffffffffu, s, o);
        if (lane == 0) gT[m][d] = -s / (float)NN;
    }

    // beta = GAMMA * mean(Q0)^1.5
    __shared__ float sred[8];
    float q = Q0[tid];
    {
        float s = q;
        #pragma unroll
        for (int o = 16; o; o >>= 1) s += __shfl_xor_sync(0xffffffffu, s, o);
        if (lane == 0) sred[warp] = s;
    }
    __syncthreads();
    if (tid == 0) {
        float t = 0.f;
        for (int w = 0; w < 8; w++) t += sred[w];
        float mq = t / (float)KK;
        gBeta = GAMMA_C * mq * sqrtf(mq);
    }

    // per-cluster state + folded exp constants from (Q0, X0)
    int k = tid;
    float x0 = X0[k * 3 + 0], x1 = X0[k * 3 + 1], x2 = X0[k * 3 + 2];
    gX[k][0] = x0; gX[k][1] = x1; gX[k][2] = x2;
    gQ[k] = q;
    float xs = x0 * x0 + x1 * x1 + x2 * x2;
    gC1[k] = -0.5f * q * LOG2E;
    gC0[k] = 1.5f * log2f(q) - 0.5f * q * xs * LOG2E;
    gDx[k] = q * LOG2E * x0;
    gDy[k] = q * LOG2E * x1;
    gDz[k] = q * LOG2E * x2;

    // R = I
    if (tid < 72) gR[tid / 9][tid % 9] = ((tid % 9) % 4 == 0) ? 1.f : 0.f;

    // zero accumulators
    for (int m = 0; m < MM; m++) {
        gL[m][k] = 0.f; gWx[m][k] = 0.f; gWy[m][k] = 0.f; gWz[m][k] = 0.f; gS2[m][k] = 0.f;
    }
}

// ------------------------------ accumulate ----------------------------------
// One warp per point; lane owns clusters [8*lane, 8*lane+8).
__global__ void __launch_bounds__(256, 2)
accum_kernel(const float* __restrict__ Vs) {
    int m    = blockIdx.x / BPM;
    int blk  = blockIdx.x % BPM;
    int warp = threadIdx.x >> 5, lane = threadIdx.x & 31;
    int k0 = lane * 8;

    float C0[8], C1[8], Dx[8], Dy[8], Dz[8];
    #pragma unroll
    for (int j = 0; j < 8; j++) {
        int k = k0 + j;
        C0[j] = gC0[k]; C1[j] = gC1[k];
        Dx[j] = gDx[k]; Dy[j] = gDy[k]; Dz[j] = gDz[k];
    }
    float R00 = gR[m][0], R01 = gR[m][1], R02 = gR[m][2];
    float R10 = gR[m][3], R11 = gR[m][4], R12 = gR[m][5];
    float R20 = gR[m][6], R21 = gR[m][7], R22 = gR[m][8];
    float tx = gT[m][0], ty = gT[m][1], tz = gT[m][2];
    float beta = gBeta;

    float aL[8], aWx[8], aWy[8], aWz[8], aS2[8];
    #pragma unroll
    for (int j = 0; j < 8; j++) { aL[j] = 0.f; aWx[j] = 0.f; aWy[j] = 0.f; aWz[j] = 0.f; aS2[j] = 0.f; }

    const float* V0 = Vs + m * 3 * NN;
    int w = blk * 8 + warp;             // warp index within this m: 0..WPM-1
    int chunk = (NN + WPM - 1) / WPM;   // contiguous chunk per warp
    int nbeg = w * chunk;
    int nend = min(NN, nbeg + chunk);

    for (int n = nbeg; n < nend; n++) {
        float vx = __ldg(V0 + n), vy = __ldg(V0 + NN + n), vz = __ldg(V0 + 2 * NN + n);
        float Tx = fmaf(R00, vx, fmaf(R01, vy, fmaf(R02, vz, tx)));
        float Ty = fmaf(R10, vx, fmaf(R11, vy, fmaf(R12, vz, ty)));
        float Tz = fmaf(R20, vx, fmaf(R21, vy, fmaf(R22, vz, tz)));
        float hT = fmaf(Tx, Tx, fmaf(Ty, Ty, Tz * Tz));
        float hv = fmaf(vx, vx, fmaf(vy, vy, vz * vz));

        float ap[8];
        #pragma unroll
        for (int j = 0; j < 8; j++) {
            float arg = fmaf(C1[j], hT, C0[j]);
            arg = fmaf(Dx[j], Tx, arg);
            arg = fmaf(Dy[j], Ty, arg);
            arg = fmaf(Dz[j], Tz, arg);
            ap[j] = ex2f(arg);
        }
        float s01 = ap[0] + ap[1], s23 = ap[2] + ap[3];
        float s45 = ap[4] + ap[5], s67 = ap[6] + ap[7];
        float ssum = (s01 + s23) + (s45 + s67);
        #pragma unroll
        for (int o = 16; o; o >>= 1) ssum += __shfl_xor_sync(0xffffffffu, ssum, o);
        float inv = rcpf(ssum + beta);

        #pragma unroll
        for (int j = 0; j < 8; j++) {
            float a = ap[j] * inv;
            aL[j]  += a;
            aWx[j] = fmaf(vx, a, aWx[j]);
            aWy[j] = fmaf(vy, a, aWy[j]);
            aWz[j] = fmaf(vz, a, aWz[j]);
            aS2[j] = fmaf(hv, a, aS2[j]);
        }
    }

    // block-level shared reduction, then one set of global atomics per block
    __shared__ float s5[5][KK];
    for (int i = threadIdx.x; i < 5 * KK; i += 256) ((float*)s5)[i] = 0.f;
    __syncthreads();
    #pragma unroll
    for (int j = 0; j < 8; j++) {
        int k = k0 + j;
        atomicAdd(&s5[0][k], aL[j]);
        atomicAdd(&s5[1][k], aWx[j]);
        atomicAdd(&s5[2][k], aWy[j]);
        atomicAdd(&s5[3][k], aWz[j]);
        atomicAdd(&s5[4][k], aS2[j]);
    }
    __syncthreads();
    int k = threadIdx.x;
    atomicAdd(&gL[m][k],  s5[0][k]);
    atomicAdd(&gWx[m][k], s5[1][k]);
    atomicAdd(&gWy[m][k], s5[2][k]);
    atomicAdd(&gWz[m][k], s5[3][k]);
    atomicAdd(&gS2[m][k], s5[4][k]);
}

// -------------------------------- solve -------------------------------------
// Single block, 256 threads (thread == cluster k).
__global__ void solve_kernel(int iter) {
    int k = threadIdx.x;
    int lane = k & 31, warp = k >> 5;

    float Lm[MM], Wrx[MM], Wry[MM], Wrz[MM], S2m[MM];
    #pragma unroll
    for (int m = 0; m < MM; m++) {
        Lm[m] = gL[m][k]; Wrx[m] = gWx[m][k]; Wry[m] = gWy[m][k]; Wrz[m] = gWz[m][k]; S2m[m] = gS2[m][k];
    }
    float Qk = gQ[k];
    float Xk0 = gX[k][0], Xk1 = gX[k][1], Xk2 = gX[k][2];

    __shared__ float sm_z[MM], sm_mX[MM][3], sm_mW[MM][3], sm_P[MM][9];
    __shared__ float sR[MM][9], sT[MM][3];
    __shared__ float red[16][8];

    for (int m = 0; m < MM; m++) {
        float b = Lm[m] * Qk;
        float wqx = Wrx[m] * Qk, wqy = Wry[m] * Qk, wqz = Wrz[m] * Qk;
        float p[16];
        p[0] = b;
        p[1] = b * Xk0;  p[2] = b * Xk1;  p[3] = b * Xk2;
        p[4] = wqx;      p[5] = wqy;      p[6] = wqz;
        p[7]  = wqx * Xk0; p[8]  = wqy * Xk0; p[9]  = wqz * Xk0;   // P[0][d]
        p[10] = wqx * Xk1; p[11] = wqy * Xk1; p[12] = wqz * Xk1;   // P[1][d]
        p[13] = wqx * Xk2; p[14] = wqy * Xk2; p[15] = wqz * Xk2;   // P[2][d]
        #pragma unroll
        for (int q = 0; q < 16; q++) {
            float v = p[q];
            #pragma unroll
            for (int o = 16; o; o >>= 1) v += __shfl_xor_sync(0xffffffffu, v, o);
            p[q] = v;
        }
        if (lane == 0) {
            #pragma unroll
            for (int q = 0; q < 16; q++) red[q][warp] = p[q];
        }
        __syncthreads();
        if (k < 16) {
            float s = 0.f;
            #pragma unroll
            for (int w = 0; w < 8; w++) s += red[k][w];
            if (k == 0)      sm_z[m] = s;
            else if (k < 4)  sm_mX[m][k - 1] = s;
            else if (k < 7)  sm_mW[m][k - 4] = s;
            else             sm_P[m][k - 7] = s;   // index e*3+d
        }
        __syncthreads();
    }

    // --- per-m SVD (double precision), 8 threads ---
    if (k < MM) {
        int m = k;
        double z = (double)sm_z[m];
        double mX[3], mW[3];
        for (int d = 0; d < 3; d++) { mX[d] = sm_mX[m][d]; mW[d] = sm_mW[m][d]; }
        double P[3][3];
        for (int e = 0; e < 3; e++)
            for (int d = 0; d < 3; d++)
                P[e][d] = (double)sm_P[m][e * 3 + d] - mX[e] * mW[d] / z;

        // A = P^T P, Jacobi eigendecomposition -> V (right singular vectors)
        double A[3][3], V[3][3];
        for (int i = 0; i < 3; i++)
            for (int j = 0; j < 3; j++) {
                A[i][j] = P[0][i] * P[0][j] + P[1][i] * P[1][j] + P[2][i] * P[2][j];
                V[i][j] = (i == j) ? 1.0 : 0.0;
            }
        for (int sw = 0; sw < 15; sw++) {
            for (int pi = 0; pi < 3; pi++) {
                int p = (pi == 2) ? 1 : 0;
                int q = (pi == 0) ? 1 : 2;
                double apq = A[p][q];
                if (apq != 0.0) {
                    double theta = (A[q][q] - A[p][p]) / (2.0 * apq);
                    double tt = ((theta >= 0.0) ? 1.0 : -1.0) / (fabs(theta) + sqrt(theta * theta + 1.0));
                    double c = 1.0 / sqrt(tt * tt + 1.0);
                    double s = tt * c;
                    int r = 3 - p - q;
                    double arp = A[r][p], arq = A[r][q];
                    A[p][p] -= tt * apq;
                    A[q][q] += tt * apq;
                    A[p][q] = 0.0; A[q][p] = 0.0;
                    double nrp = c * arp - s * arq, nrq = s * arp + c * arq;
                    A[r][p] = nrp; A[p][r] = nrp; A[r][q] = nrq; A[q][r] = nrq;
                    for (int rr = 0; rr < 3; rr++) {
                        double vp = V[rr][p], vq = V[rr][q];
                        V[rr][p] = c * vp - s * vq;
                        V[rr][q] = s * vp + c * vq;
                    }
                }
            }
        }
        double ev[3] = { A[0][0], A[1][1], A[2][2] };
        // sort eigenpairs descending (columns of V)
        for (int pass = 0; pass < 3; pass++) {
            int i = (pass == 1) ? 1 : 0, j = i + 1;
            if (ev[j] > ev[i]) {
                double te = ev[i]; ev[i] = ev[j]; ev[j] = te;
                for (int r = 0; r < 3; r++) { double tv = V[r][i]; V[r][i] = V[r][j]; V[r][j] = tv; }
            }
        }
        double u[3][3];   // u[i][e] = left singular vector i
        for (int i = 0; i < 2; i++) {
            double sg = sqrt(fmax(ev[i], 0.0));
            double inv = (sg > 1e-30) ? 1.0 / sg : 0.0;
            for (int e = 0; e < 3; e++)
                u[i][e] = (P[e][0] * V[0][i] + P[e][1] * V[1][i] + P[e][2] * V[2][i]) * inv;
        }
        // clean orthonormality
        {
            double n0 = sqrt(u[0][0]*u[0][0] + u[0][1]*u[0][1] + u[0][2]*u[0][2]);
            double in0 = (n0 > 1e-30) ? 1.0 / n0 : 0.0;
            for (int e = 0; e < 3; e++) u[0][e] *= in0;
            double d01 = u[0][0]*u[1][0] + u[0][1]*u[1][1] + u[0][2]*u[1][2];
            for (int e = 0; e < 3; e++) u[1][e] -= d01 * u[0][e];
            double n1 = sqrt(u[1][0]*u[1][0] + u[1][1]*u[1][1] + u[1][2]*u[1][2]);
            double in1 = (n1 > 1e-30) ? 1.0 / n1 : 0.0;
            for (int e = 0; e < 3; e++) u[1][e] *= in1;
        }
        // u2 = u0 x u1  (det(U) = +1)
        u[2][0] = u[0][1]*u[1][2] - u[0][2]*u[1][1];
        u[2][1] = u[0][2]*u[1][0] - u[0][0]*u[1][2];
        u[2][2] = u[0][0]*u[1][1] - u[0][1]*u[1][0];
        double detV = V[0][0]*(V[1][1]*V[2][2] - V[1][2]*V[2][1])
                    - V[0][1]*(V[1][0]*V[2][2] - V[1][2]*V[2][0])
                    + V[0][2]*(V[1][0]*V[2][1] - V[1][1]*V[2][0]);
        double dlt = (detV >= 0.0) ? 1.0 : -1.0;

        double R[3][3];
        for (int a = 0; a < 3; a++)
            for (int b = 0; b < 3; b++)
                R[a][b] = u[0][a]*V[b][0] + u[1][a]*V[b][1] + dlt*u[2][a]*V[b][2];
        double t[3];
        for (int a = 0; a < 3; a++)
            t[a] = (mX[a] - (R[a][0]*mW[0] + R[a][1]*mW[1] + R[a][2]*mW[2])) / z;

        for (int a = 0; a < 3; a++) {
            for (int b = 0; b < 3; b++) {
                float rf = (float)R[a][b];
                sR[m][a*3+b] = rf; gR[m][a*3+b] = rf;
            }
            float tf = (float)t[a];
            sT[m][a] = tf; gT[m][a] = tf;
        }
    }
    __syncthreads();

    // --- per-cluster epilogue: den, Num, X update, wn, Q update, new consts ---
    float den = 0.f;
    #pragma unroll
    for (int m = 0; m < MM; m++) den += Lm[m];

    float Nx = 0.f, Ny = 0.f, Nz = 0.f, sA = 0.f;
    #pragma unroll
    for (int m = 0; m < MM; m++) {
        float RWx = sR[m][0]*Wrx[m] + sR[m][1]*Wry[m] + sR[m][2]*Wrz[m];
        float RWy = sR[m][3]*Wrx[m] + sR[m][4]*Wry[m] + sR[m][5]*Wrz[m];
        float RWz = sR[m][6]*Wrx[m] + sR[m][7]*Wry[m] + sR[m][8]*Wrz[m];
        float txm = sT[m][0], tym = sT[m][1], tzm = sT[m][2];
        Nx += RWx + txm * Lm[m];
        Ny += RWy + tym * Lm[m];
        Nz += RWz + tzm * Lm[m];
        sA += S2m[m] + 2.f * (txm*RWx + tym*RWy + tzm*RWz)
            + (txm*txm + tym*tym + tzm*tzm) * Lm[m];
    }

    float Xn0, Xn1, Xn2;
    if (iter > FIX_ITER) {
        float id = 1.f / den;
        Xn0 = Nx * id; Xn1 = Ny * id; Xn2 = Nz * id;
    } else {
        Xn0 = Xk0; Xn1 = Xk1; Xn2 = Xk2;
    }
    float xn2 = Xn0*Xn0 + Xn1*Xn1 + Xn2*Xn2;
    float wn = sA + xn2 * den - 2.f * (Xn0*Nx + Xn1*Ny + Xn2*Nz);
    float Qn = 3.f * den / (wn + 3.f * den * EPS_C);

    gX[k][0] = Xn0; gX[k][1] = Xn1; gX[k][2] = Xn2;
    gQ[k] = Qn;
    gC1[k] = -0.5f * Qn * LOG2E;
    gC0[k] = 1.5f * log2f(Qn) - 0.5f * Qn * xn2 * LOG2E;
    gDx[k] = Qn * LOG2E * Xn0;
    gDy[k] = Qn * LOG2E * Xn1;
    gDz[k] = Qn * LOG2E * Xn2;

    #pragma unroll
    for (int m = 0; m < MM; m++) {
        gL[m][k] = 0.f; gWx[m][k] = 0.f; gWy[m][k] = 0.f; gWz[m][k] = 0.f; gS2[m][k] = 0.f;
    }
}

// ------------------------------- finalize -----------------------------------
// out = [TVs (8,3,8192) | R (8,3,3) | t (8,3) | X (256,3)]  (float32, C-order)
__global__ void finalize_kernel(const float* __restrict__ Vs, float* __restrict__ out) {
    int idx = blockIdx.x * blockDim.x + threadIdx.x;
    if (idx < MM * 3 * NN) {
        int n = idx % NN;
        int md = idx / NN;
        int m = md / 3, d = md % 3;
        const float* V0 = Vs + m * 3 * NN;
        float vx = V0[n], vy = V0[NN + n], vz = V0[2 * NN + n];
        out[idx] = fmaf(gR[m][d*3+0], vx, fmaf(gR[m][d*3+1], vy, fmaf(gR[m][d*3+2], vz, gT[m][d])));
    }
    if (idx < 72)  out[196608 + idx] = gR[idx / 9][idx % 9];
    if (idx < 24)  out[196680 + idx] = gT[idx / 3][idx % 3];
    if (idx < 768) out[196704 + idx] = gX[idx / 3][idx % 3];
}

// ------------------------------ launch --------------------------------------
extern "C" void kernel_launch(void* const* d_in, const int* in_sizes, int n_in,
                              void* d_out, int out_size) {
    const float* Vs = (const float*)d_in[0];
    const float* X0 = (const float*)d_in[1];
    const float* Q0 = (const float*)d_in[2];
    float* out = (float*)d_out;

    init_kernel<<<1, 256>>>(Vs, X0, Q0);
    for (int i = 0; i < NUM_ITERS; i++) {
        accum_kernel<<<MM * BPM, 256>>>(Vs);
        solve_kernel<<<1, 256>>>(i);
    }
    finalize_kernel<<<(MM * 3 * NN + 255) / 256, 256>>>(Vs, out);
}

// round 3
// speedup vs baseline: 2.2412x; 2.2412x over previous
#include <cuda_runtime.h>
#include <math.h>

#define MM 8
#define NN 8192
#define KK 256
#define NUM_ITERS 6
#define FIX_ITER 1

#define LOG2E 1.44269504088896340736f
#define EPS_C 0.01f
#define GAMMA_C 0.005f

#define BPM 37            // blocks per shape m (8*37 = 296 blocks = 2/SM)
#define WPM (BPM * 8)     // warps per shape

static __device__ __forceinline__ float ex2f(float x) {
    float y; asm("ex2.approx.f32 %0, %1;" : "=f"(y) : "f"(x)); return y;
}
static __device__ __forceinline__ float rcpf(float x) {
    float y; asm("rcp.approx.f32 %0, %1;" : "=f"(y) : "f"(x)); return y;
}
static __device__ __forceinline__ float rsqf(float x) {
    float y; asm("rsqrt.approx.f32 %0, %1;" : "=f"(y) : "f"(x)); return y;
}

// ------------- persistent device state (no allocations allowed) -------------
__device__ float gL[MM][KK], gWx[MM][KK], gWy[MM][KK], gWz[MM][KK], gS2[MM][KK];
__device__ float gR[MM][9];     // row-major R[a][b]
__device__ float gT[MM][3];
__device__ float gX[KK][3];
__device__ float gQ[KK];
__device__ float gC0[KK], gC1[KK], gDx[KK], gDy[KK], gDz[KK];
__device__ float gBeta;

// ------------------------------- init ---------------------------------------
__global__ void init_kernel(const float* __restrict__ Vs,
                            const float* __restrict__ X0,
                            const float* __restrict__ Q0) {
    int tid = threadIdx.x;
    int lane = tid & 31, warp = tid >> 5;

    // t0[m][d] = -mean_n Vs[m,d,n]; 24 (m,d) pairs across 8 warps
    for (int p = warp; p < 24; p += 8) {
        int m = p / 3, d = p % 3;
        const float* src = Vs + (m * 3 + d) * NN;
        float s = 0.f;
        for (int n = lane; n < NN; n += 32) s += src[n];
        #pragma unroll
        for (int o = 16; o; o >>= 1) s += __shfl_xor_sync(0xffffffffu, s, o);
        if (lane == 0) gT[m][d] = -s / (float)NN;
    }

    // beta = GAMMA * mean(Q0)^1.5
    __shared__ float sred[8];
    float q = Q0[tid];
    {
        float s = q;
        #pragma unroll
        for (int o = 16; o; o >>= 1) s += __shfl_xor_sync(0xffffffffu, s, o);
        if (lane == 0) sred[warp] = s;
    }
    __syncthreads();
    if (tid == 0) {
        float t = 0.f;
        for (int w = 0; w < 8; w++) t += sred[w];
        float mq = t / (float)KK;
        gBeta = GAMMA_C * mq * sqrtf(mq);
    }

    // per-cluster state + folded exp constants from (Q0, X0)
    int k = tid;
    float x0 = X0[k * 3 + 0], x1 = X0[k * 3 + 1], x2 = X0[k * 3 + 2];
    gX[k][0] = x0; gX[k][1] = x1; gX[k][2] = x2;
    gQ[k] = q;
    float xs = x0 * x0 + x1 * x1 + x2 * x2;
    gC1[k] = -0.5f * q * LOG2E;
    gC0[k] = 1.5f * log2f(q) - 0.5f * q * xs * LOG2E;
    gDx[k] = q * LOG2E * x0;
    gDy[k] = q * LOG2E * x1;
    gDz[k] = q * LOG2E * x2;

    // R = I
    if (tid < 72) gR[tid / 9][tid % 9] = ((tid % 9) % 4 == 0) ? 1.f : 0.f;

    // zero accumulators
    for (int m = 0; m < MM; m++) {
        gL[m][k] = 0.f; gWx[m][k] = 0.f; gWy[m][k] = 0.f; gWz[m][k] = 0.f; gS2[m][k] = 0.f;
    }
}

// ------------------------------ accumulate ----------------------------------
// One warp per point; lane owns clusters [8*lane, 8*lane+8).
__global__ void __launch_bounds__(256, 2)
accum_kernel(const float* __restrict__ Vs) {
    int m    = blockIdx.x / BPM;
    int blk  = blockIdx.x % BPM;
    int warp = threadIdx.x >> 5, lane = threadIdx.x & 31;
    int k0 = lane * 8;

    float C0[8], C1[8], Dx[8], Dy[8], Dz[8];
    #pragma unroll
    for (int j = 0; j < 8; j++) {
        int k = k0 + j;
        C0[j] = gC0[k]; C1[j] = gC1[k];
        Dx[j] = gDx[k]; Dy[j] = gDy[k]; Dz[j] = gDz[k];
    }
    float R00 = gR[m][0], R01 = gR[m][1], R02 = gR[m][2];
    float R10 = gR[m][3], R11 = gR[m][4], R12 = gR[m][5];
    float R20 = gR[m][6], R21 = gR[m][7], R22 = gR[m][8];
    float tx = gT[m][0], ty = gT[m][1], tz = gT[m][2];
    float beta = gBeta;

    float aL[8], aWx[8], aWy[8], aWz[8], aS2[8];
    #pragma unroll
    for (int j = 0; j < 8; j++) { aL[j] = 0.f; aWx[j] = 0.f; aWy[j] = 0.f; aWz[j] = 0.f; aS2[j] = 0.f; }

    const float* V0 = Vs + m * 3 * NN;
    int w = blk * 8 + warp;             // warp index within this m: 0..WPM-1
    int chunk = (NN + WPM - 1) / WPM;   // contiguous chunk per warp
    int nbeg = w * chunk;
    int nend = min(NN, nbeg + chunk);

    for (int n = nbeg; n < nend; n++) {
        float vx = __ldg(V0 + n), vy = __ldg(V0 + NN + n), vz = __ldg(V0 + 2 * NN + n);
        float Tx = fmaf(R00, vx, fmaf(R01, vy, fmaf(R02, vz, tx)));
        float Ty = fmaf(R10, vx, fmaf(R11, vy, fmaf(R12, vz, ty)));
        float Tz = fmaf(R20, vx, fmaf(R21, vy, fmaf(R22, vz, tz)));
        float hT = fmaf(Tx, Tx, fmaf(Ty, Ty, Tz * Tz));
        float hv = fmaf(vx, vx, fmaf(vy, vy, vz * vz));

        float ap[8];
        #pragma unroll
        for (int j = 0; j < 8; j++) {
            float arg = fmaf(C1[j], hT, C0[j]);
            arg = fmaf(Dx[j], Tx, arg);
            arg = fmaf(Dy[j], Ty, arg);
            arg = fmaf(Dz[j], Tz, arg);
            ap[j] = ex2f(arg);
        }
        float s01 = ap[0] + ap[1], s23 = ap[2] + ap[3];
        float s45 = ap[4] + ap[5], s67 = ap[6] + ap[7];
        float ssum = (s01 + s23) + (s45 + s67);
        #pragma unroll
        for (int o = 16; o; o >>= 1) ssum += __shfl_xor_sync(0xffffffffu, ssum, o);
        float inv = rcpf(ssum + beta);

        #pragma unroll
        for (int j = 0; j < 8; j++) {
            float a = ap[j] * inv;
            aL[j]  += a;
            aWx[j] = fmaf(vx, a, aWx[j]);
            aWy[j] = fmaf(vy, a, aWy[j]);
            aWz[j] = fmaf(vz, a, aWz[j]);
            aS2[j] = fmaf(hv, a, aS2[j]);
        }
    }

    // block-level shared reduction, then one set of global atomics per block
    __shared__ float s5[5][KK];
    for (int i = threadIdx.x; i < 5 * KK; i += 256) ((float*)s5)[i] = 0.f;
    __syncthreads();
    #pragma unroll
    for (int j = 0; j < 8; j++) {
        int k = k0 + j;
        atomicAdd(&s5[0][k], aL[j]);
        atomicAdd(&s5[1][k], aWx[j]);
        atomicAdd(&s5[2][k], aWy[j]);
        atomicAdd(&s5[3][k], aWz[j]);
        atomicAdd(&s5[4][k], aS2[j]);
    }
    __syncthreads();
    int k = threadIdx.x;
    atomicAdd(&gL[m][k],  s5[0][k]);
    atomicAdd(&gWx[m][k], s5[1][k]);
    atomicAdd(&gWy[m][k], s5[2][k]);
    atomicAdd(&gWz[m][k], s5[3][k]);
    atomicAdd(&gS2[m][k], s5[4][k]);
}

// -------------------------------- solve -------------------------------------
// Single block, 256 threads (thread == cluster k). All math fp32 now — the
// fp64 div/sqrt sequences were ~54us/call on a latency-bound single warp.
__global__ void solve_kernel(int iter) {
    int k = threadIdx.x;
    int lane = k & 31, warp = k >> 5;

    float Lm[MM], Wrx[MM], Wry[MM], Wrz[MM], S2m[MM];
    #pragma unroll
    for (int m = 0; m < MM; m++) {
        Lm[m] = gL[m][k]; Wrx[m] = gWx[m][k]; Wry[m] = gWy[m][k]; Wrz[m] = gWz[m][k]; S2m[m] = gS2[m][k];
    }
    float Qk = gQ[k];
    float Xk0 = gX[k][0], Xk1 = gX[k][1], Xk2 = gX[k][2];

    __shared__ float sm_z[MM], sm_mX[MM][3], sm_mW[MM][3], sm_P[MM][9];
    __shared__ float sR[MM][9], sT[MM][3];
    __shared__ float red[16][8];

    for (int m = 0; m < MM; m++) {
        float b = Lm[m] * Qk;
        float wqx = Wrx[m] * Qk, wqy = Wry[m] * Qk, wqz = Wrz[m] * Qk;
        float p[16];
        p[0] = b;
        p[1] = b * Xk0;  p[2] = b * Xk1;  p[3] = b * Xk2;
        p[4] = wqx;      p[5] = wqy;      p[6] = wqz;
        p[7]  = wqx * Xk0; p[8]  = wqy * Xk0; p[9]  = wqz * Xk0;   // P[0][d]
        p[10] = wqx * Xk1; p[11] = wqy * Xk1; p[12] = wqz * Xk1;   // P[1][d]
        p[13] = wqx * Xk2; p[14] = wqy * Xk2; p[15] = wqz * Xk2;   // P[2][d]
        #pragma unroll
        for (int q = 0; q < 16; q++) {
            float v = p[q];
            #pragma unroll
            for (int o = 16; o; o >>= 1) v += __shfl_xor_sync(0xffffffffu, v, o);
            p[q] = v;
        }
        if (lane == 0) {
            #pragma unroll
            for (int q = 0; q < 16; q++) red[q][warp] = p[q];
        }
        __syncthreads();
        if (k < 16) {
            float s = 0.f;
            #pragma unroll
            for (int w = 0; w < 8; w++) s += red[k][w];
            if (k == 0)      sm_z[m] = s;
            else if (k < 4)  sm_mX[m][k - 1] = s;
            else if (k < 7)  sm_mW[m][k - 4] = s;
            else             sm_P[m][k - 7] = s;   // index e*3+d
        }
        __syncthreads();
    }

    // --- per-m SVD (fp32, Jacobi on P^T P), 8 threads ---
    if (k < MM) {
        int m = k;
        float z = sm_z[m];
        float invz = 1.f / z;
        float mX[3], mW[3];
        for (int d = 0; d < 3; d++) { mX[d] = sm_mX[m][d]; mW[d] = sm_mW[m][d]; }
        float P[3][3];
        for (int e = 0; e < 3; e++)
            for (int d = 0; d < 3; d++)
                P[e][d] = sm_P[m][e * 3 + d] - mX[e] * mW[d] * invz;

        // A = P^T P, Jacobi eigendecomposition -> V (right singular vectors)
        float A[3][3], V[3][3];
        for (int i = 0; i < 3; i++)
            for (int j = 0; j < 3; j++) {
                A[i][j] = P[0][i] * P[0][j] + P[1][i] * P[1][j] + P[2][i] * P[2][j];
                V[i][j] = (i == j) ? 1.f : 0.f;
            }
        #pragma unroll 1
        for (int sw = 0; sw < 8; sw++) {
            #pragma unroll
            for (int pi = 0; pi < 3; pi++) {
                int p = (pi == 2) ? 1 : 0;
                int q = (pi == 0) ? 1 : 2;
                float apq = A[p][q];
                if (fabsf(apq) > 1e-30f) {
                    float theta = (A[q][q] - A[p][p]) * 0.5f / apq;
                    float tt = ((theta >= 0.f) ? 1.f : -1.f) / (fabsf(theta) + sqrtf(fmaf(theta, theta, 1.f)));
                    float c = rsqf(fmaf(tt, tt, 1.f));
                    float s = tt * c;
                    int r = 3 - p - q;
                    float arp = A[r][p], arq = A[r][q];
                    A[p][p] -= tt * apq;
                    A[q][q] += tt * apq;
                    A[p][q] = 0.f; A[q][p] = 0.f;
                    float nrp = c * arp - s * arq, nrq = s * arp + c * arq;
                    A[r][p] = nrp; A[p][r] = nrp; A[r][q] = nrq; A[q][r] = nrq;
                    #pragma unroll
                    for (int rr = 0; rr < 3; rr++) {
                        float vp = V[rr][p], vq = V[rr][q];
                        V[rr][p] = c * vp - s * vq;
                        V[rr][q] = s * vp + c * vq;
                    }
                }
            }
        }
        float ev[3] = { A[0][0], A[1][1], A[2][2] };
        // sort eigenpairs descending (columns of V)
        #pragma unroll
        for (int pass = 0; pass < 3; pass++) {
            int i = (pass == 1) ? 1 : 0, j = i + 1;
            if (ev[j] > ev[i]) {
                float te = ev[i]; ev[i] = ev[j]; ev[j] = te;
                for (int r = 0; r < 3; r++) { float tv = V[r][i]; V[r][i] = V[r][j]; V[r][j] = tv; }
            }
        }
        float u[3][3];   // u[i][e] = left singular vector i
        #pragma unroll
        for (int i = 0; i < 2; i++) {
            float sg2 = fmaxf(ev[i], 0.f);
            float inv = (sg2 > 1e-30f) ? rsqf(sg2) : 0.f;
            for (int e = 0; e < 3; e++)
                u[i][e] = (P[e][0] * V[0][i] + P[e][1] * V[1][i] + P[e][2] * V[2][i]) * inv;
        }
        // clean orthonormality (Gram-Schmidt)
        {
            float n0 = u[0][0]*u[0][0] + u[0][1]*u[0][1] + u[0][2]*u[0][2];
            float in0 = (n0 > 1e-30f) ? rsqf(n0) : 0.f;
            for (int e = 0; e < 3; e++) u[0][e] *= in0;
            float d01 = u[0][0]*u[1][0] + u[0][1]*u[1][1] + u[0][2]*u[1][2];
            for (int e = 0; e < 3; e++) u[1][e] -= d01 * u[0][e];
            float n1 = u[1][0]*u[1][0] + u[1][1]*u[1][1] + u[1][2]*u[1][2];
            float in1 = (n1 > 1e-30f) ? rsqf(n1) : 0.f;
            for (int e = 0; e < 3; e++) u[1][e] *= in1;
        }
        // u2 = u0 x u1  (det(U) = +1)
        u[2][0] = u[0][1]*u[1][2] - u[0][2]*u[1][1];
        u[2][1] = u[0][2]*u[1][0] - u[0][0]*u[1][2];
        u[2][2] = u[0][0]*u[1][1] - u[0][1]*u[1][0];
        float detV = V[0][0]*(V[1][1]*V[2][2] - V[1][2]*V[2][1])
                   - V[0][1]*(V[1][0]*V[2][2] - V[1][2]*V[2][0])
                   + V[0][2]*(V[1][0]*V[2][1] - V[1][1]*V[2][0]);
        float dlt = (detV >= 0.f) ? 1.f : -1.f;

        float R[3][3];
        for (int a = 0; a < 3; a++)
            for (int b = 0; b < 3; b++)
                R[a][b] = u[0][a]*V[b][0] + u[1][a]*V[b][1] + dlt*u[2][a]*V[b][2];
        float t[3];
        for (int a = 0; a < 3; a++)
            t[a] = (mX[a] - (R[a][0]*mW[0] + R[a][1]*mW[1] + R[a][2]*mW[2])) * invz;

        for (int a = 0; a < 3; a++) {
            for (int b = 0; b < 3; b++) {
                float rf = R[a][b];
                sR[m][a*3+b] = rf; gR[m][a*3+b] = rf;
            }
            float tf = t[a];
            sT[m][a] = tf; gT[m][a] = tf;
        }
    }
    __syncthreads();

    // --- per-cluster epilogue: den, Num, X update, wn, Q update, new consts ---
    float den = 0.f;
    #pragma unroll
    for (int m = 0; m < MM; m++) den += Lm[m];

    float Nx = 0.f, Ny = 0.f, Nz = 0.f, sA = 0.f;
    #pragma unroll
    for (int m = 0; m < MM; m++) {
        float RWx = sR[m][0]*Wrx[m] + sR[m][1]*Wry[m] + sR[m][2]*Wrz[m];
        float RWy = sR[m][3]*Wrx[m] + sR[m][4]*Wry[m] + sR[m][5]*Wrz[m];
        float RWz = sR[m][6]*Wrx[m] + sR[m][7]*Wry[m] + sR[m][8]*Wrz[m];
        float txm = sT[m][0], tym = sT[m][1], tzm = sT[m][2];
        Nx += RWx + txm * Lm[m];
        Ny += RWy + tym * Lm[m];
        Nz += RWz + tzm * Lm[m];
        sA += S2m[m] + 2.f * (txm*RWx + tym*RWy + tzm*RWz)
            + (txm*txm + tym*tym + tzm*tzm) * Lm[m];
    }

    float Xn0, Xn1, Xn2;
    if (iter > FIX_ITER) {
        float id = 1.f / den;
        Xn0 = Nx * id; Xn1 = Ny * id; Xn2 = Nz * id;
    } else {
        Xn0 = Xk0; Xn1 = Xk1; Xn2 = Xk2;
    }
    float xn2 = Xn0*Xn0 + Xn1*Xn1 + Xn2*Xn2;
    float wn = sA + xn2 * den - 2.f * (Xn0*Nx + Xn1*Ny + Xn2*Nz);
    float Qn = 3.f * den / (wn + 3.f * den * EPS_C);

    gX[k][0] = Xn0; gX[k][1] = Xn1; gX[k][2] = Xn2;
    gQ[k] = Qn;
    gC1[k] = -0.5f * Qn * LOG2E;
    gC0[k] = 1.5f * log2f(Qn) - 0.5f * Qn * xn2 * LOG2E;
    gDx[k] = Qn * LOG2E * Xn0;
    gDy[k] = Qn * LOG2E * Xn1;
    gDz[k] = Qn * LOG2E * Xn2;

    #pragma unroll
    for (int m = 0; m < MM; m++) {
        gL[m][k] = 0.f; gWx[m][k] = 0.f; gWy[m][k] = 0.f; gWz[m][k] = 0.f; gS2[m][k] = 0.f;
    }
}

// ------------------------------- finalize -----------------------------------
// out = [TVs (8,3,8192) | R (8,3,3) | t (8,3) | X (256,3)]  (float32, C-order)
__global__ void finalize_kernel(const float* __restrict__ Vs, float* __restrict__ out) {
    int idx = blockIdx.x * blockDim.x + threadIdx.x;
    if (idx < MM * 3 * NN) {
        int n = idx % NN;
        int md = idx / NN;
        int m = md / 3, d = md % 3;
        const float* V0 = Vs + m * 3 * NN;
        float vx = V0[n], vy = V0[NN + n], vz = V0[2 * NN + n];
        out[idx] = fmaf(gR[m][d*3+0], vx, fmaf(gR[m][d*3+1], vy, fmaf(gR[m][d*3+2], vz, gT[m][d])));
    }
    if (idx < 72)  out[196608 + idx] = gR[idx / 9][idx % 9];
    if (idx < 24)  out[196680 + idx] = gT[idx / 3][idx % 3];
    if (idx < 768) out[196704 + idx] = gX[idx / 3][idx % 3];
}

// ------------------------------ launch --------------------------------------
extern "C" void kernel_launch(void* const* d_in, const int* in_sizes, int n_in,
                              void* d_out, int out_size) {
    const float* Vs = (const float*)d_in[0];
    const float* X0 = (const float*)d_in[1];
    const float* Q0 = (const float*)d_in[2];
    float* out = (float*)d_out;

    init_kernel<<<1, 256>>>(Vs, X0, Q0);
    for (int i = 0; i < NUM_ITERS; i++) {
        accum_kernel<<<MM * BPM, 256>>>(Vs);
        solve_kernel<<<1, 256>>>(i);
    }
    finalize_kernel<<<(MM * 3 * NN + 255) / 256, 256>>>(Vs, out);
}

// round 4
// speedup vs baseline: 2.5572x; 1.1410x over previous
#include <cuda_runtime.h>
#include <math.h>

#define MM 8
#define NN 8192
#define KK 256
#define NUM_ITERS 6
#define FIX_ITER 1

#define LOG2E 1.44269504088896340736f
#define EPS_C 0.01f
#define GAMMA_C 0.005f

#define BPM 37            // blocks per shape m (8*37 = 296 blocks = 2/SM exactly)
#define NPB 222           // points per block (37*222 = 8214 >= 8192; last block 200)

static __device__ __forceinline__ float ex2f(float x) {
    float y; asm("ex2.approx.f32 %0, %1;" : "=f"(y) : "f"(x)); return y;
}
static __device__ __forceinline__ float rcpf(float x) {
    float y; asm("rcp.approx.f32 %0, %1;" : "=f"(y) : "f"(x)); return y;
}
static __device__ __forceinline__ float rsqf(float x) {
    float y; asm("rsqrt.approx.f32 %0, %1;" : "=f"(y) : "f"(x)); return y;
}

// ------------- persistent device state (no allocations allowed) -------------
__device__ float gL[MM][KK], gWx[MM][KK], gWy[MM][KK], gWz[MM][KK], gS2[MM][KK];
__device__ float gR[MM][9];     // row-major R[a][b]
__device__ float gT[MM][3];
__device__ float gX[KK][3];
__device__ float gQ[KK];
__device__ float gC0[KK], gC1[KK], gDx[KK], gDy[KK], gDz[KK];
__device__ float gBeta;

// ------------------------------- init ---------------------------------------
__global__ void init_kernel(const float* __restrict__ Vs,
                            const float* __restrict__ X0,
                            const float* __restrict__ Q0) {
    int tid = threadIdx.x;
    int lane = tid & 31, warp = tid >> 5;

    for (int p = warp; p < 24; p += 8) {
        int m = p / 3, d = p % 3;
        const float* src = Vs + (m * 3 + d) * NN;
        float s = 0.f;
        for (int n = lane; n < NN; n += 32) s += src[n];
        #pragma unroll
        for (int o = 16; o; o >>= 1) s += __shfl_xor_sync(0xffffffffu, s, o);
        if (lane == 0) gT[m][d] = -s / (float)NN;
    }

    __shared__ float sred[8];
    float q = Q0[tid];
    {
        float s = q;
        #pragma unroll
        for (int o = 16; o; o >>= 1) s += __shfl_xor_sync(0xffffffffu, s, o);
        if (lane == 0) sred[warp] = s;
    }
    __syncthreads();
    if (tid == 0) {
        float t = 0.f;
        for (int w = 0; w < 8; w++) t += sred[w];
        float mq = t / (float)KK;
        gBeta = GAMMA_C * mq * sqrtf(mq);
    }

    int k = tid;
    float x0 = X0[k * 3 + 0], x1 = X0[k * 3 + 1], x2 = X0[k * 3 + 2];
    gX[k][0] = x0; gX[k][1] = x1; gX[k][2] = x2;
    gQ[k] = q;
    float xs = x0 * x0 + x1 * x1 + x2 * x2;
    gC1[k] = -0.5f * q * LOG2E;
    gC0[k] = 1.5f * log2f(q) - 0.5f * q * xs * LOG2E;
    gDx[k] = q * LOG2E * x0;
    gDy[k] = q * LOG2E * x1;
    gDz[k] = q * LOG2E * x2;

    if (tid < 72) gR[tid / 9][tid % 9] = ((tid % 9) % 4 == 0) ? 1.f : 0.f;

    for (int m = 0; m < MM; m++) {
        gL[m][k] = 0.f; gWx[m][k] = 0.f; gWy[m][k] = 0.f; gWz[m][k] = 0.f; gS2[m][k] = 0.f;
    }
}

// ------------------------------ accumulate ----------------------------------
// Block stages its 222 points into shared (one coalesced read), then one warp
// per point-subrange; lane owns clusters [8*lane, 8*lane+8). Inner loop reads
// points via broadcast LDS (29cyc) instead of per-point LDG (250+cyc), and is
// unrolled x2 so two shfl-butterfly chains interleave.
__global__ void __launch_bounds__(256, 2)
accum_kernel(const float* __restrict__ Vs) {
    int m    = blockIdx.x / BPM;
    int blk  = blockIdx.x % BPM;
    int tid  = threadIdx.x;
    int warp = tid >> 5, lane = tid & 31;
    int k0 = lane * 8;

    int n0 = blk * NPB;
    int count = min(NPB, NN - n0);

    __shared__ float sv[3][NPB];
    __shared__ float s5[5][KK];

    const float* V0 = Vs + m * 3 * NN + n0;
    #pragma unroll
    for (int r = 0; r < 3; r++)
        for (int j = tid; j < count; j += 256)
            sv[r][j] = __ldg(V0 + r * NN + j);
    for (int i = tid; i < 5 * KK; i += 256) ((float*)s5)[i] = 0.f;

    float C0[8], C1[8], Dx[8], Dy[8], Dz[8];
    #pragma unroll
    for (int j = 0; j < 8; j++) {
        int k = k0 + j;
        C0[j] = gC0[k]; C1[j] = gC1[k];
        Dx[j] = gDx[k]; Dy[j] = gDy[k]; Dz[j] = gDz[k];
    }
    float R00 = gR[m][0], R01 = gR[m][1], R02 = gR[m][2];
    float R10 = gR[m][3], R11 = gR[m][4], R12 = gR[m][5];
    float R20 = gR[m][6], R21 = gR[m][7], R22 = gR[m][8];
    float tx = gT[m][0], ty = gT[m][1], tz = gT[m][2];
    float beta = gBeta;

    float aL[8], aWx[8], aWy[8], aWz[8], aS2[8];
    #pragma unroll
    for (int j = 0; j < 8; j++) { aL[j] = 0.f; aWx[j] = 0.f; aWy[j] = 0.f; aWz[j] = 0.f; aS2[j] = 0.f; }

    __syncthreads();

    int beg = warp * 28;
    int end = min(beg + 28, count);

    #pragma unroll 2
    for (int i = beg; i < end; i++) {
        float vx = sv[0][i], vy = sv[1][i], vz = sv[2][i];
        float Tx = fmaf(R00, vx, fmaf(R01, vy, fmaf(R02, vz, tx)));
        float Ty = fmaf(R10, vx, fmaf(R11, vy, fmaf(R12, vz, ty)));
        float Tz = fmaf(R20, vx, fmaf(R21, vy, fmaf(R22, vz, tz)));
        float hT = fmaf(Tx, Tx, fmaf(Ty, Ty, Tz * Tz));
        float hv = fmaf(vx, vx, fmaf(vy, vy, vz * vz));

        float ap[8];
        #pragma unroll
        for (int j = 0; j < 8; j++) {
            float arg = fmaf(C1[j], hT, C0[j]);
            arg = fmaf(Dx[j], Tx, arg);
            arg = fmaf(Dy[j], Ty, arg);
            arg = fmaf(Dz[j], Tz, arg);
            ap[j] = ex2f(arg);
        }
        float s01 = ap[0] + ap[1], s23 = ap[2] + ap[3];
        float s45 = ap[4] + ap[5], s67 = ap[6] + ap[7];
        float ssum = (s01 + s23) + (s45 + s67);
        #pragma unroll
        for (int o = 16; o; o >>= 1) ssum += __shfl_xor_sync(0xffffffffu, ssum, o);
        float inv = rcpf(ssum + beta);

        #pragma unroll
        for (int j = 0; j < 8; j++) {
            float a = ap[j] * inv;
            aL[j]  += a;
            aWx[j] = fmaf(vx, a, aWx[j]);
            aWy[j] = fmaf(vy, a, aWy[j]);
            aWz[j] = fmaf(vz, a, aWz[j]);
            aS2[j] = fmaf(hv, a, aS2[j]);
        }
    }

    // block-level shared reduction, then one set of global atomics per block
    #pragma unroll
    for (int j = 0; j < 8; j++) {
        int k = k0 + j;
        atomicAdd(&s5[0][k], aL[j]);
        atomicAdd(&s5[1][k], aWx[j]);
        atomicAdd(&s5[2][k], aWy[j]);
        atomicAdd(&s5[3][k], aWz[j]);
        atomicAdd(&s5[4][k], aS2[j]);
    }
    __syncthreads();
    int k = tid;
    atomicAdd(&gL[m][k],  s5[0][k]);
    atomicAdd(&gWx[m][k], s5[1][k]);
    atomicAdd(&gWy[m][k], s5[2][k]);
    atomicAdd(&gWz[m][k], s5[3][k]);
    atomicAdd(&gS2[m][k], s5[4][k]);
}

// -------------------------------- solve -------------------------------------
// Single block, 256 threads. Phase 1: warp w reduces shape m=w (all 8 shapes
// in parallel). Then 8 threads do fp32 3x3 SVDs; epilogue per cluster.
__global__ void solve_kernel(int iter) {
    int k = threadIdx.x;
    int lane = k & 31, warp = k >> 5;

    __shared__ float sm_z[MM], sm_mX[MM][3], sm_mW[MM][3], sm_P[MM][9];
    __shared__ float sR[MM][9], sT[MM][3];

    // --- phase 1: per-shape moment reduction, warp == shape ---
    {
        int m = warp;
        float Qk_, x0_, x1_, x2_;
        float p[16];
        #pragma unroll
        for (int q = 0; q < 16; q++) p[q] = 0.f;
        #pragma unroll
        for (int j = 0; j < 8; j++) {
            int kk = lane + 32 * j;
            float L = gL[m][kk], wx = gWx[m][kk], wy = gWy[m][kk], wz = gWz[m][kk];
            Qk_ = gQ[kk];
            x0_ = gX[kk][0]; x1_ = gX[kk][1]; x2_ = gX[kk][2];
            float b = L * Qk_;
            float wqx = wx * Qk_, wqy = wy * Qk_, wqz = wz * Qk_;
            p[0] += b;
            p[1] = fmaf(b, x0_, p[1]);  p[2] = fmaf(b, x1_, p[2]);  p[3] = fmaf(b, x2_, p[3]);
            p[4] += wqx; p[5] += wqy; p[6] += wqz;
            p[7]  = fmaf(wqx, x0_, p[7]);  p[8]  = fmaf(wqy, x0_, p[8]);  p[9]  = fmaf(wqz, x0_, p[9]);
            p[10] = fmaf(wqx, x1_, p[10]); p[11] = fmaf(wqy, x1_, p[11]); p[12] = fmaf(wqz, x1_, p[12]);
            p[13] = fmaf(wqx, x2_, p[13]); p[14] = fmaf(wqy, x2_, p[14]); p[15] = fmaf(wqz, x2_, p[15]);
        }
        #pragma unroll
        for (int q = 0; q < 16; q++) {
            float v = p[q];
            #pragma unroll
            for (int o = 16; o; o >>= 1) v += __shfl_xor_sync(0xffffffffu, v, o);
            p[q] = v;
        }
        if (lane == 0) {
            sm_z[m] = p[0];
            sm_mX[m][0] = p[1]; sm_mX[m][1] = p[2]; sm_mX[m][2] = p[3];
            sm_mW[m][0] = p[4]; sm_mW[m][1] = p[5]; sm_mW[m][2] = p[6];
            #pragma unroll
            for (int q = 0; q < 9; q++) sm_P[m][q] = p[7 + q];
        }
    }
    __syncthreads();

    // --- per-m SVD (fp32, Jacobi on P^T P), 8 threads ---
    if (k < MM) {
        int m = k;
        float z = sm_z[m];
        float invz = 1.f / z;
        float mX[3], mW[3];
        for (int d = 0; d < 3; d++) { mX[d] = sm_mX[m][d]; mW[d] = sm_mW[m][d]; }
        float P[3][3];
        for (int e = 0; e < 3; e++)
            for (int d = 0; d < 3; d++)
                P[e][d] = sm_P[m][e * 3 + d] - mX[e] * mW[d] * invz;

        float A[3][3], V[3][3];
        for (int i = 0; i < 3; i++)
            for (int j = 0; j < 3; j++) {
                A[i][j] = P[0][i] * P[0][j] + P[1][i] * P[1][j] + P[2][i] * P[2][j];
                V[i][j] = (i == j) ? 1.f : 0.f;
            }
        #pragma unroll 1
        for (int sw = 0; sw < 8; sw++) {
            #pragma unroll
            for (int pi = 0; pi < 3; pi++) {
                int p = (pi == 2) ? 1 : 0;
                int q = (pi == 0) ? 1 : 2;
                float apq = A[p][q];
                if (fabsf(apq) > 1e-30f) {
                    float theta = (A[q][q] - A[p][p]) * 0.5f / apq;
                    float tt = ((theta >= 0.f) ? 1.f : -1.f) / (fabsf(theta) + sqrtf(fmaf(theta, theta, 1.f)));
                    float c = rsqf(fmaf(tt, tt, 1.f));
                    float s = tt * c;
                    int r = 3 - p - q;
                    float arp = A[r][p], arq = A[r][q];
                    A[p][p] -= tt * apq;
                    A[q][q] += tt * apq;
                    A[p][q] = 0.f; A[q][p] = 0.f;
                    float nrp = c * arp - s * arq, nrq = s * arp + c * arq;
                    A[r][p] = nrp; A[p][r] = nrp; A[r][q] = nrq; A[q][r] = nrq;
                    #pragma unroll
                    for (int rr = 0; rr < 3; rr++) {
                        float vp = V[rr][p], vq = V[rr][q];
                        V[rr][p] = c * vp - s * vq;
                        V[rr][q] = s * vp + c * vq;
                    }
                }
            }
        }
        float ev[3] = { A[0][0], A[1][1], A[2][2] };
        #pragma unroll
        for (int pass = 0; pass < 3; pass++) {
            int i = (pass == 1) ? 1 : 0, j = i + 1;
            if (ev[j] > ev[i]) {
                float te = ev[i]; ev[i] = ev[j]; ev[j] = te;
                for (int r = 0; r < 3; r++) { float tv = V[r][i]; V[r][i] = V[r][j]; V[r][j] = tv; }
            }
        }
        float u[3][3];
        #pragma unroll
        for (int i = 0; i < 2; i++) {
            float sg2 = fmaxf(ev[i], 0.f);
            float inv = (sg2 > 1e-30f) ? rsqf(sg2) : 0.f;
            for (int e = 0; e < 3; e++)
                u[i][e] = (P[e][0] * V[0][i] + P[e][1] * V[1][i] + P[e][2] * V[2][i]) * inv;
        }
        {
            float n0 = u[0][0]*u[0][0] + u[0][1]*u[0][1] + u[0][2]*u[0][2];
            float in0 = (n0 > 1e-30f) ? rsqf(n0) : 0.f;
            for (int e = 0; e < 3; e++) u[0][e] *= in0;
            float d01 = u[0][0]*u[1][0] + u[0][1]*u[1][1] + u[0][2]*u[1][2];
            for (int e = 0; e < 3; e++) u[1][e] -= d01 * u[0][e];
            float n1 = u[1][0]*u[1][0] + u[1][1]*u[1][1] + u[1][2]*u[1][2];
            float in1 = (n1 > 1e-30f) ? rsqf(n1) : 0.f;
            for (int e = 0; e < 3; e++) u[1][e] *= in1;
        }
        u[2][0] = u[0][1]*u[1][2] - u[0][2]*u[1][1];
        u[2][1] = u[0][2]*u[1][0] - u[0][0]*u[1][2];
        u[2][2] = u[0][0]*u[1][1] - u[0][1]*u[1][0];
        float detV = V[0][0]*(V[1][1]*V[2][2] - V[1][2]*V[2][1])
                   - V[0][1]*(V[1][0]*V[2][2] - V[1][2]*V[2][0])
                   + V[0][2]*(V[1][0]*V[2][1] - V[1][1]*V[2][0]);
        float dlt = (detV >= 0.f) ? 1.f : -1.f;

        float R[3][3];
        for (int a = 0; a < 3; a++)
            for (int b = 0; b < 3; b++)
                R[a][b] = u[0][a]*V[b][0] + u[1][a]*V[b][1] + dlt*u[2][a]*V[b][2];
        float t[3];
        for (int a = 0; a < 3; a++)
            t[a] = (mX[a] - (R[a][0]*mW[0] + R[a][1]*mW[1] + R[a][2]*mW[2])) * invz;

        for (int a = 0; a < 3; a++) {
            for (int b = 0; b < 3; b++) {
                float rf = R[a][b];
                sR[m][a*3+b] = rf; gR[m][a*3+b] = rf;
            }
            float tf = t[a];
            sT[m][a] = tf; gT[m][a] = tf;
        }
    }
    __syncthreads();

    // --- per-cluster epilogue ---
    float Lm[MM], Wrx[MM], Wry[MM], Wrz[MM], S2m[MM];
    #pragma unroll
    for (int m = 0; m < MM; m++) {
        Lm[m] = gL[m][k]; Wrx[m] = gWx[m][k]; Wry[m] = gWy[m][k]; Wrz[m] = gWz[m][k]; S2m[m] = gS2[m][k];
    }
    float Xk0 = gX[k][0], Xk1 = gX[k][1], Xk2 = gX[k][2];

    float den = 0.f;
    #pragma unroll
    for (int m = 0; m < MM; m++) den += Lm[m];

    float Nx = 0.f, Ny = 0.f, Nz = 0.f, sA = 0.f;
    #pragma unroll
    for (int m = 0; m < MM; m++) {
        float RWx = sR[m][0]*Wrx[m] + sR[m][1]*Wry[m] + sR[m][2]*Wrz[m];
        float RWy = sR[m][3]*Wrx[m] + sR[m][4]*Wry[m] + sR[m][5]*Wrz[m];
        float RWz = sR[m][6]*Wrx[m] + sR[m][7]*Wry[m] + sR[m][8]*Wrz[m];
        float txm = sT[m][0], tym = sT[m][1], tzm = sT[m][2];
        Nx += RWx + txm * Lm[m];
        Ny += RWy + tym * Lm[m];
        Nz += RWz + tzm * Lm[m];
        sA += S2m[m] + 2.f * (txm*RWx + tym*RWy + tzm*RWz)
            + (txm*txm + tym*tym + tzm*tzm) * Lm[m];
    }

    float Xn0, Xn1, Xn2;
    if (iter > FIX_ITER) {
        float id = 1.f / den;
        Xn0 = Nx * id; Xn1 = Ny * id; Xn2 = Nz * id;
    } else {
        Xn0 = Xk0; Xn1 = Xk1; Xn2 = Xk2;
    }
    float xn2 = Xn0*Xn0 + Xn1*Xn1 + Xn2*Xn2;
    float wn = sA + xn2 * den - 2.f * (Xn0*Nx + Xn1*Ny + Xn2*Nz);
    float Qn = 3.f * den / (wn + 3.f * den * EPS_C);

    gX[k][0] = Xn0; gX[k][1] = Xn1; gX[k][2] = Xn2;
    gQ[k] = Qn;
    gC1[k] = -0.5f * Qn * LOG2E;
    gC0[k] = 1.5f * log2f(Qn) - 0.5f * Qn * xn2 * LOG2E;
    gDx[k] = Qn * LOG2E * Xn0;
    gDy[k] = Qn * LOG2E * Xn1;
    gDz[k] = Qn * LOG2E * Xn2;

    #pragma unroll
    for (int m = 0; m < MM; m++) {
        gL[m][k] = 0.f; gWx[m][k] = 0.f; gWy[m][k] = 0.f; gWz[m][k] = 0.f; gS2[m][k] = 0.f;
    }
}

// ------------------------------- finalize -----------------------------------
// out = [TVs (8,3,8192) | R (8,3,3) | t (8,3) | X (256,3)]  (float32, C-order)
__global__ void finalize_kernel(const float* __restrict__ Vs, float* __restrict__ out) {
    int idx = blockIdx.x * blockDim.x + threadIdx.x;
    if (idx < MM * 3 * NN) {
        int n = idx % NN;
        int md = idx / NN;
        int m = md / 3, d = md % 3;
        const float* V0 = Vs + m * 3 * NN;
        float vx = V0[n], vy = V0[NN + n], vz = V0[2 * NN + n];
        out[idx] = fmaf(gR[m][d*3+0], vx, fmaf(gR[m][d*3+1], vy, fmaf(gR[m][d*3+2], vz, gT[m][d])));
    }
    if (idx < 72)  out[196608 + idx] = gR[idx / 9][idx % 9];
    if (idx < 24)  out[196680 + idx] = gT[idx / 3][idx % 3];
    if (idx < 768) out[196704 + idx] = gX[idx / 3][idx % 3];
}

// ------------------------------ launch --------------------------------------
extern "C" void kernel_launch(void* const* d_in, const int* in_sizes, int n_in,
                              void* d_out, int out_size) {
    const float* Vs = (const float*)d_in[0];
    const float* X0 = (const float*)d_in[1];
    const float* Q0 = (const float*)d_in[2];
    float* out = (float*)d_out;

    init_kernel<<<1, 256>>>(Vs, X0, Q0);
    for (int i = 0; i < NUM_ITERS; i++) {
        accum_kernel<<<MM * BPM, 256>>>(Vs);
        solve_kernel<<<1, 256>>>(i);
    }
    finalize_kernel<<<(MM * 3 * NN + 255) / 256, 256>>>(Vs, out);
}

// round 5
// speedup vs baseline: 3.1970x; 1.2502x over previous
#include <cuda_runtime.h>
#include <math.h>

#define MM 8
#define NN 8192
#define KK 256
#define NUM_ITERS 6
#define FIX_ITER 1

#define LOG2E 1.44269504088896340736f
#define EPS_C 0.01f
#define GAMMA_C 0.005f

#define BPM 37            // blocks per shape m
#define NPB 222           // points per block
#define GRID (MM * BPM)   // 296 = 2 CTAs/SM on 148 SMs -> all resident

typedef unsigned long long u64;

static __device__ __forceinline__ float ex2f(float x) {
    float y; asm("ex2.approx.f32 %0, %1;" : "=f"(y) : "f"(x)); return y;
}
static __device__ __forceinline__ float rcpf(float x) {
    float y; asm("rcp.approx.f32 %0, %1;" : "=f"(y) : "f"(x)); return y;
}
static __device__ __forceinline__ float rsqf(float x) {
    float y; asm("rsqrt.approx.f32 %0, %1;" : "=f"(y) : "f"(x)); return y;
}
static __device__ __forceinline__ u64 pk2(float lo, float hi) {
    u64 r; asm("mov.b64 %0, {%1, %2};" : "=l"(r)
               : "r"(__float_as_uint(lo)), "r"(__float_as_uint(hi)));
    return r;
}
static __device__ __forceinline__ void upk2(u64 v, float& lo, float& hi) {
    unsigned a, b; asm("mov.b64 {%0, %1}, %2;" : "=r"(a), "=r"(b) : "l"(v));
    lo = __uint_as_float(a); hi = __uint_as_float(b);
}
static __device__ __forceinline__ u64 fma2(u64 a, u64 b, u64 c) {
    u64 d; asm("fma.rn.f32x2 %0, %1, %2, %3;" : "=l"(d) : "l"(a), "l"(b), "l"(c)); return d;
}
static __device__ __forceinline__ u64 mul2(u64 a, u64 b) {
    u64 d; asm("mul.rn.f32x2 %0, %1, %2;" : "=l"(d) : "l"(a), "l"(b)); return d;
}
static __device__ __forceinline__ u64 add2(u64 a, u64 b) {
    u64 d; asm("add.rn.f32x2 %0, %1, %2;" : "=l"(d) : "l"(a), "l"(b)); return d;
}

// ------------- persistent device state (no allocations allowed) -------------
__device__ float gL[MM][KK], gWx[MM][KK], gWy[MM][KK], gWz[MM][KK], gS2[MM][KK];
__device__ float gR[MM][9];     // row-major R[a][b]
__device__ float gT[MM][3];
__device__ float gX[KK][3];
__device__ float gQ[KK];
__device__ float gC0[KK], gC1[KK], gDx[KK], gDy[KK], gDz[KK];
__device__ float gBeta;

__device__ unsigned g_arrive = 0;
__device__ volatile unsigned g_phase = 0;

static __device__ __forceinline__ void grid_barrier() {
    __syncthreads();
    if (threadIdx.x == 0) {
        unsigned p = g_phase;
        __threadfence();
        unsigned rank = atomicAdd(&g_arrive, 1u);
        if (rank == GRID - 1) {
            g_arrive = 0;
            __threadfence();
            g_phase = p + 1;
        } else {
            while (g_phase == p) __nanosleep(32);
        }
        __threadfence();
    }
    __syncthreads();
}

// ------------------------------ fused kernel ---------------------------------
__global__ void __launch_bounds__(256, 2)
fused_kernel(const float* __restrict__ Vs,
             const float* __restrict__ X0,
             const float* __restrict__ Q0,
             float* __restrict__ out) {
    int bid = blockIdx.x, tid = threadIdx.x;
    int lane = tid & 31, warp = tid >> 5;

    // shared memory
    __shared__ float sTx[2 * NPB], sTy[2 * NPB], sTz[2 * NPB], shT[2 * NPB];
    __shared__ float s5[5][KK];
    __shared__ float sRt[12];
    __shared__ float sred[8];
    // solve-only (block 0)
    __shared__ float sRold[72], sTold[24], sM[72], sTn[24];
    __shared__ float smz[8], smx[24], smw[24], smp[72];
    // finalize
    __shared__ float fR[72], fT[24];

    // ------------------------------ init ------------------------------------
    if (bid < 24) {
        int m = bid / 3, d = bid % 3;
        const float* src = Vs + (m * 3 + d) * NN;
        float s = 0.f;
        for (int n = tid; n < NN; n += 256) s += __ldg(src + n);
        #pragma unroll
        for (int o = 16; o; o >>= 1) s += __shfl_xor_sync(0xffffffffu, s, o);
        if (lane == 0) sred[warp] = s;
        __syncthreads();
        if (tid == 0) {
            float t = 0.f;
            for (int w = 0; w < 8; w++) t += sred[w];
            gT[m][d] = -t / (float)NN;
        }
    } else if (bid == 24) {
        float q = __ldg(Q0 + tid);
        {
            float s = q;
            #pragma unroll
            for (int o = 16; o; o >>= 1) s += __shfl_xor_sync(0xffffffffu, s, o);
            if (lane == 0) sred[warp] = s;
        }
        __syncthreads();
        if (tid == 0) {
            float t = 0.f;
            for (int w = 0; w < 8; w++) t += sred[w];
            float mq = t / (float)KK;
            gBeta = GAMMA_C * mq * sqrtf(mq);
        }
        int k = tid;
        float x0 = __ldg(X0 + k * 3 + 0), x1 = __ldg(X0 + k * 3 + 1), x2 = __ldg(X0 + k * 3 + 2);
        gX[k][0] = x0; gX[k][1] = x1; gX[k][2] = x2;
        gQ[k] = q;
        float xs = x0 * x0 + x1 * x1 + x2 * x2;
        gC1[k] = -0.5f * q * LOG2E;
        gC0[k] = 1.5f * log2f(q) - 0.5f * q * xs * LOG2E;
        gDx[k] = q * LOG2E * x0;
        gDy[k] = q * LOG2E * x1;
        gDz[k] = q * LOG2E * x2;
        if (tid < 72) ((float*)gR)[tid] = ((tid % 9) % 4 == 0) ? 1.f : 0.f;
    } else if (bid == 25) {
        for (int i = tid; i < MM * KK; i += 256) {
            ((float*)gL)[i] = 0.f; ((float*)gWx)[i] = 0.f; ((float*)gWy)[i] = 0.f;
            ((float*)gWz)[i] = 0.f; ((float*)gS2)[i] = 0.f;
        }
    }
    grid_barrier();

    // ---------------------------- iterations ---------------------------------
    int m   = bid / BPM;
    int blk = bid % BPM;
    int n0 = blk * NPB;
    int count = min(NPB, NN - n0);
    const float* V0 = Vs + m * 3 * NN + n0;

    for (int it = 0; it < NUM_ITERS; it++) {
        // ---- stage: transform points into T-space, duplicated pairs ----
        if (tid < 9)       sRt[tid] = __ldcg(&gR[m][tid]);
        else if (tid < 12) sRt[tid] = __ldcg(&gT[m][tid - 9]);
        for (int i = tid; i < 5 * KK; i += 256) ((float*)s5)[i] = 0.f;
        __syncthreads();
        if (tid < count) {
            float vx = __ldg(V0 + tid), vy = __ldg(V0 + NN + tid), vz = __ldg(V0 + 2 * NN + tid);
            float Tx = fmaf(sRt[0], vx, fmaf(sRt[1], vy, fmaf(sRt[2], vz, sRt[9])));
            float Ty = fmaf(sRt[3], vx, fmaf(sRt[4], vy, fmaf(sRt[5], vz, sRt[10])));
            float Tz = fmaf(sRt[6], vx, fmaf(sRt[7], vy, fmaf(sRt[8], vz, sRt[11])));
            float hT = fmaf(Tx, Tx, fmaf(Ty, Ty, Tz * Tz));
            sTx[2 * tid] = Tx; sTx[2 * tid + 1] = Tx;
            sTy[2 * tid] = Ty; sTy[2 * tid + 1] = Ty;
            sTz[2 * tid] = Tz; sTz[2 * tid + 1] = Tz;
            shT[2 * tid] = hT; shT[2 * tid + 1] = hT;
        }

        // packed per-lane cluster constants: pair jj -> clusters (lane+64jj, lane+64jj+32)
        u64 C0p[4], C1p[4], DxP[4], DyP[4], DzP[4];
        #pragma unroll
        for (int jj = 0; jj < 4; jj++) {
            int ka = lane + 64 * jj, kb = ka + 32;
            C0p[jj] = pk2(__ldcg(&gC0[ka]), __ldcg(&gC0[kb]));
            C1p[jj] = pk2(__ldcg(&gC1[ka]), __ldcg(&gC1[kb]));
            DxP[jj] = pk2(__ldcg(&gDx[ka]), __ldcg(&gDx[kb]));
            DyP[jj] = pk2(__ldcg(&gDy[ka]), __ldcg(&gDy[kb]));
            DzP[jj] = pk2(__ldcg(&gDz[ka]), __ldcg(&gDz[kb]));
        }
        float beta = __ldcg(&gBeta);

        u64 aLp[4], aWxp[4], aWyp[4], aWzp[4], aSp[4];
        #pragma unroll
        for (int jj = 0; jj < 4; jj++) {
            aLp[jj] = 0ull; aWxp[jj] = 0ull; aWyp[jj] = 0ull; aWzp[jj] = 0ull; aSp[jj] = 0ull;
        }
        __syncthreads();

        int beg = warp * 28;
        int end = min(beg + 28, count);

        #pragma unroll 2
        for (int i = beg; i < end; i++) {
            u64 Txp = *(const u64*)&sTx[2 * i];
            u64 Typ = *(const u64*)&sTy[2 * i];
            u64 Tzp = *(const u64*)&sTz[2 * i];
            u64 hTp = *(const u64*)&shT[2 * i];

            float ap[8];
            #pragma unroll
            for (int jj = 0; jj < 4; jj++) {
                u64 arg = fma2(C1p[jj], hTp, C0p[jj]);
                arg = fma2(DxP[jj], Txp, arg);
                arg = fma2(DyP[jj], Typ, arg);
                arg = fma2(DzP[jj], Tzp, arg);
                float lo, hi; upk2(arg, lo, hi);
                ap[2 * jj]     = ex2f(lo);
                ap[2 * jj + 1] = ex2f(hi);
            }
            float ssum = ((ap[0] + ap[1]) + (ap[2] + ap[3]))
                       + ((ap[4] + ap[5]) + (ap[6] + ap[7]));
            #pragma unroll
            for (int o = 16; o; o >>= 1) ssum += __shfl_xor_sync(0xffffffffu, ssum, o);
            float inv = rcpf(ssum + beta);
            u64 invp = pk2(inv, inv);

            #pragma unroll
            for (int jj = 0; jj < 4; jj++) {
                u64 app = pk2(ap[2 * jj], ap[2 * jj + 1]);
                u64 a = mul2(app, invp);
                aLp[jj]  = add2(aLp[jj], a);
                aWxp[jj] = fma2(Txp, a, aWxp[jj]);
                aWyp[jj] = fma2(Typ, a, aWyp[jj]);
                aWzp[jj] = fma2(Tzp, a, aWzp[jj]);
                aSp[jj]  = fma2(hTp, a, aSp[jj]);
            }
        }

        // ---- block-level shared reduction ----
        #pragma unroll
        for (int jj = 0; jj < 4; jj++) {
            int ka = lane + 64 * jj, kb = ka + 32;
            float lo, hi;
            upk2(aLp[jj],  lo, hi); atomicAdd(&s5[0][ka], lo); atomicAdd(&s5[0][kb], hi);
            upk2(aWxp[jj], lo, hi); atomicAdd(&s5[1][ka], lo); atomicAdd(&s5[1][kb], hi);
            upk2(aWyp[jj], lo, hi); atomicAdd(&s5[2][ka], lo); atomicAdd(&s5[2][kb], hi);
            upk2(aWzp[jj], lo, hi); atomicAdd(&s5[3][ka], lo); atomicAdd(&s5[3][kb], hi);
            upk2(aSp[jj],  lo, hi); atomicAdd(&s5[4][ka], lo); atomicAdd(&s5[4][kb], hi);
        }
        __syncthreads();
        atomicAdd(&gL[m][tid],  s5[0][tid]);
        atomicAdd(&gWx[m][tid], s5[1][tid]);
        atomicAdd(&gWy[m][tid], s5[2][tid]);
        atomicAdd(&gWz[m][tid], s5[3][tid]);
        atomicAdd(&gS2[m][tid], s5[4][tid]);

        grid_barrier();

        // ------------------------------ solve (block 0) ----------------------
        if (bid == 0) {
            // snapshot old R, t
            if (tid < 72) sRold[tid] = __ldcg(((const float*)gR) + tid);
            if (tid < 24) sTold[tid] = __ldcg(((const float*)gT) + tid);
            __syncthreads();

            // phase 1: warp == shape moment reduction (raw-space recovery)
            {
                int mm = warp;
                const float* Ro = &sRold[mm * 9];
                float tox = sTold[mm * 3 + 0], toy = sTold[mm * 3 + 1], toz = sTold[mm * 3 + 2];
                float p[16];
                #pragma unroll
                for (int q = 0; q < 16; q++) p[q] = 0.f;
                #pragma unroll
                for (int j = 0; j < 8; j++) {
                    int kk = lane + 32 * j;
                    float L   = __ldcg(&gL[mm][kk]);
                    float WTx = __ldcg(&gWx[mm][kk]);
                    float WTy = __ldcg(&gWy[mm][kk]);
                    float WTz = __ldcg(&gWz[mm][kk]);
                    float Q   = __ldcg(&gQ[kk]);
                    float x0  = __ldcg(&gX[kk][0]), x1 = __ldcg(&gX[kk][1]), x2 = __ldcg(&gX[kk][2]);
                    float WX = WTx - tox * L, WY = WTy - toy * L, WZ = WTz - toz * L;
                    float wrx = Ro[0] * WX + Ro[3] * WY + Ro[6] * WZ;   // Rold^T W
                    float wry = Ro[1] * WX + Ro[4] * WY + Ro[7] * WZ;
                    float wrz = Ro[2] * WX + Ro[5] * WY + Ro[8] * WZ;
                    float b = L * Q;
                    float wqx = wrx * Q, wqy = wry * Q, wqz = wrz * Q;
                    p[0] += b;
                    p[1] = fmaf(b, x0, p[1]);  p[2] = fmaf(b, x1, p[2]);  p[3] = fmaf(b, x2, p[3]);
                    p[4] += wqx; p[5] += wqy; p[6] += wqz;
                    p[7]  = fmaf(wqx, x0, p[7]);  p[8]  = fmaf(wqy, x0, p[8]);  p[9]  = fmaf(wqz, x0, p[9]);
                    p[10] = fmaf(wqx, x1, p[10]); p[11] = fmaf(wqy, x1, p[11]); p[12] = fmaf(wqz, x1, p[12]);
                    p[13] = fmaf(wqx, x2, p[13]); p[14] = fmaf(wqy, x2, p[14]); p[15] = fmaf(wqz, x2, p[15]);
                }
                #pragma unroll
                for (int q = 0; q < 16; q++) {
                    float v = p[q];
                    #pragma unroll
                    for (int o = 16; o; o >>= 1) v += __shfl_xor_sync(0xffffffffu, v, o);
                    p[q] = v;
                }
                if (lane == 0) {
                    smz[mm] = p[0];
                    smx[mm * 3 + 0] = p[1]; smx[mm * 3 + 1] = p[2]; smx[mm * 3 + 2] = p[3];
                    smw[mm * 3 + 0] = p[4]; smw[mm * 3 + 1] = p[5]; smw[mm * 3 + 2] = p[6];
                    #pragma unroll
                    for (int q = 0; q < 9; q++) smp[mm * 9 + q] = p[7 + q];
                }
            }
            __syncthreads();

            // 3x3 SVD per shape (8 threads, fp32 Jacobi)
            if (tid < MM) {
                int mm = tid;
                float z = smz[mm];
                float invz = 1.f / z;
                float mX[3], mW[3];
                for (int d = 0; d < 3; d++) { mX[d] = smx[mm * 3 + d]; mW[d] = smw[mm * 3 + d]; }
                float P[3][3];
                for (int e = 0; e < 3; e++)
                    for (int d = 0; d < 3; d++)
                        P[e][d] = smp[mm * 9 + e * 3 + d] - mX[e] * mW[d] * invz;

                float A[3][3], V[3][3];
                for (int i = 0; i < 3; i++)
                    for (int j = 0; j < 3; j++) {
                        A[i][j] = P[0][i] * P[0][j] + P[1][i] * P[1][j] + P[2][i] * P[2][j];
                        V[i][j] = (i == j) ? 1.f : 0.f;
                    }
                #pragma unroll 1
                for (int sw = 0; sw < 8; sw++) {
                    #pragma unroll
                    for (int pi = 0; pi < 3; pi++) {
                        int p = (pi == 2) ? 1 : 0;
                        int q = (pi == 0) ? 1 : 2;
                        float apq = A[p][q];
                        if (fabsf(apq) > 1e-30f) {
                            float theta = (A[q][q] - A[p][p]) * 0.5f / apq;
                            float tt = ((theta >= 0.f) ? 1.f : -1.f) / (fabsf(theta) + sqrtf(fmaf(theta, theta, 1.f)));
                            float c = rsqf(fmaf(tt, tt, 1.f));
                            float s = tt * c;
                            int r = 3 - p - q;
                            float arp = A[r][p], arq = A[r][q];
                            A[p][p] -= tt * apq;
                            A[q][q] += tt * apq;
                            A[p][q] = 0.f; A[q][p] = 0.f;
                            float nrp = c * arp - s * arq, nrq = s * arp + c * arq;
                            A[r][p] = nrp; A[p][r] = nrp; A[r][q] = nrq; A[q][r] = nrq;
                            #pragma unroll
                            for (int rr = 0; rr < 3; rr++) {
                                float vp = V[rr][p], vq = V[rr][q];
                                V[rr][p] = c * vp - s * vq;
                                V[rr][q] = s * vp + c * vq;
                            }
                        }
                    }
                }
                float ev[3] = { A[0][0], A[1][1], A[2][2] };
                #pragma unroll
                for (int pass = 0; pass < 3; pass++) {
                    int i = (pass == 1) ? 1 : 0, j = i + 1;
                    if (ev[j] > ev[i]) {
                        float te = ev[i]; ev[i] = ev[j]; ev[j] = te;
                        for (int r = 0; r < 3; r++) { float tv = V[r][i]; V[r][i] = V[r][j]; V[r][j] = tv; }
                    }
                }
                float u[3][3];
                #pragma unroll
                for (int i = 0; i < 2; i++) {
                    float sg2 = fmaxf(ev[i], 0.f);
                    float inv = (sg2 > 1e-30f) ? rsqf(sg2) : 0.f;
                    for (int e = 0; e < 3; e++)
                        u[i][e] = (P[e][0] * V[0][i] + P[e][1] * V[1][i] + P[e][2] * V[2][i]) * inv;
                }
                {
                    float n0 = u[0][0]*u[0][0] + u[0][1]*u[0][1] + u[0][2]*u[0][2];
                    float in0 = (n0 > 1e-30f) ? rsqf(n0) : 0.f;
                    for (int e = 0; e < 3; e++) u[0][e] *= in0;
                    float d01 = u[0][0]*u[1][0] + u[0][1]*u[1][1] + u[0][2]*u[1][2];
                    for (int e = 0; e < 3; e++) u[1][e] -= d01 * u[0][e];
                    float n1 = u[1][0]*u[1][0] + u[1][1]*u[1][1] + u[1][2]*u[1][2];
                    float in1 = (n1 > 1e-30f) ? rsqf(n1) : 0.f;
                    for (int e = 0; e < 3; e++) u[1][e] *= in1;
                }
                u[2][0] = u[0][1]*u[1][2] - u[0][2]*u[1][1];
                u[2][1] = u[0][2]*u[1][0] - u[0][0]*u[1][2];
                u[2][2] = u[0][0]*u[1][1] - u[0][1]*u[1][0];
                float detV = V[0][0]*(V[1][1]*V[2][2] - V[1][2]*V[2][1])
                           - V[0][1]*(V[1][0]*V[2][2] - V[1][2]*V[2][0])
                           + V[0][2]*(V[1][0]*V[2][1] - V[1][1]*V[2][0]);
                float dlt = (detV >= 0.f) ? 1.f : -1.f;

                float R[3][3];
                for (int a = 0; a < 3; a++)
                    for (int b = 0; b < 3; b++)
                        R[a][b] = u[0][a]*V[b][0] + u[1][a]*V[b][1] + dlt*u[2][a]*V[b][2];
                float t[3];
                for (int a = 0; a < 3; a++)
                    t[a] = (mX[a] - (R[a][0]*mW[0] + R[a][1]*mW[1] + R[a][2]*mW[2])) * invz;

                const float* Ro = &sRold[mm * 9];
                for (int a = 0; a < 3; a++) {
                    for (int b = 0; b < 3; b++) {
                        gR[mm][a * 3 + b] = R[a][b];
                        // M = Rnew * Rold^T
                        sM[mm * 9 + a * 3 + b] = R[a][0] * Ro[b * 3 + 0]
                                               + R[a][1] * Ro[b * 3 + 1]
                                               + R[a][2] * Ro[b * 3 + 2];
                    }
                    gT[mm][a] = t[a];
                    sTn[mm * 3 + a] = t[a];
                }
            }
            __syncthreads();

            // epilogue: per-cluster X/Q update (thread == cluster)
            {
                int k = tid;
                float Xk0 = __ldcg(&gX[k][0]), Xk1 = __ldcg(&gX[k][1]), Xk2 = __ldcg(&gX[k][2]);
                float den = 0.f, Nx = 0.f, Ny = 0.f, Nz = 0.f, sA = 0.f;
                #pragma unroll
                for (int mm = 0; mm < MM; mm++) {
                    float L   = __ldcg(&gL[mm][k]);
                    float WTx = __ldcg(&gWx[mm][k]);
                    float WTy = __ldcg(&gWy[mm][k]);
                    float WTz = __ldcg(&gWz[mm][k]);
                    float ST  = __ldcg(&gS2[mm][k]);
                    float tox = sTold[mm * 3 + 0], toy = sTold[mm * 3 + 1], toz = sTold[mm * 3 + 2];
                    float tnx = sTn[mm * 3 + 0],  tny = sTn[mm * 3 + 1],  tnz = sTn[mm * 3 + 2];
                    float WX = WTx - tox * L, WY = WTy - toy * L, WZ = WTz - toz * L;
                    const float* Mm = &sM[mm * 9];
                    float RWx = Mm[0] * WX + Mm[1] * WY + Mm[2] * WZ;
                    float RWy = Mm[3] * WX + Mm[4] * WY + Mm[5] * WZ;
                    float RWz = Mm[6] * WX + Mm[7] * WY + Mm[8] * WZ;
                    float S2 = ST - 2.f * (tox * WTx + toy * WTy + toz * WTz)
                             + (tox * tox + toy * toy + toz * toz) * L;
                    den += L;
                    Nx += RWx + tnx * L;
                    Ny += RWy + tny * L;
                    Nz += RWz + tnz * L;
                    sA += S2 + 2.f * (tnx * RWx + tny * RWy + tnz * RWz)
                        + (tnx * tnx + tny * tny + tnz * tnz) * L;
                }

                float Xn0, Xn1, Xn2;
                if (it > FIX_ITER) {
                    float id = 1.f / den;
                    Xn0 = Nx * id; Xn1 = Ny * id; Xn2 = Nz * id;
                } else {
                    Xn0 = Xk0; Xn1 = Xk1; Xn2 = Xk2;
                }
                float xn2 = Xn0 * Xn0 + Xn1 * Xn1 + Xn2 * Xn2;
                float wn = sA + xn2 * den - 2.f * (Xn0 * Nx + Xn1 * Ny + Xn2 * Nz);
                float Qn = 3.f * den / (wn + 3.f * den * EPS_C);

                gX[k][0] = Xn0; gX[k][1] = Xn1; gX[k][2] = Xn2;
                gQ[k] = Qn;
                gC1[k] = -0.5f * Qn * LOG2E;
                gC0[k] = 1.5f * log2f(Qn) - 0.5f * Qn * xn2 * LOG2E;
                gDx[k] = Qn * LOG2E * Xn0;
                gDy[k] = Qn * LOG2E * Xn1;
                gDz[k] = Qn * LOG2E * Xn2;

                #pragma unroll
                for (int mm = 0; mm < MM; mm++) {
                    gL[mm][k] = 0.f; gWx[mm][k] = 0.f; gWy[mm][k] = 0.f;
                    gWz[mm][k] = 0.f; gS2[mm][k] = 0.f;
                }
            }
        }
        grid_barrier();
    }

    // ------------------------------ finalize ---------------------------------
    if (tid < 72) fR[tid] = __ldcg(((const float*)gR) + tid);
    if (tid < 24) fT[tid] = __ldcg(((const float*)gT) + tid);
    __syncthreads();
    {
        const int TOT = MM * 3 * NN;                  // 196608
        int per = (TOT + GRID - 1) / GRID;            // 665
        int s = bid * per, e = min(s + per, TOT);
        for (int idx = s + tid; idx < e; idx += 256) {
            int n = idx % NN;
            int md = idx / NN;
            int mq = md / 3;
            const float* Vm = Vs + mq * 3 * NN;
            float vx = __ldg(Vm + n), vy = __ldg(Vm + NN + n), vz = __ldg(Vm + 2 * NN + n);
            out[idx] = fmaf(fR[3 * md], vx, fmaf(fR[3 * md + 1], vy, fmaf(fR[3 * md + 2], vz, fT[md])));
        }
        if (bid == 0) {
            if (tid < 72) out[196608 + tid] = fR[tid];
            if (tid < 24) out[196680 + tid] = fT[tid];
            for (int i = tid; i < 768; i += 256)
                out[196704 + i] = __ldcg(((const float*)gX) + i);
        }
    }
}

// ------------------------------ launch --------------------------------------
extern "C" void kernel_launch(void* const* d_in, const int* in_sizes, int n_in,
                              void* d_out, int out_size) {
    const float* Vs = (const float*)d_in[0];
    const float* X0 = (const float*)d_in[1];
    const float* Q0 = (const float*)d_in[2];
    float* out = (float*)d_out;

    fused_kernel<<<GRID, 256>>>(Vs, X0, Q0, out);
}

// round 6
// speedup vs baseline: 3.6652x; 1.1465x over previous
#include <cuda_runtime.h>
#include <math.h>

#define MM 8
#define NN 8192
#define KK 256
#define NUM_ITERS 6
#define FIX_ITER 1

#define LOG2E 1.44269504088896340736f
#define EPS_C 0.01f
#define GAMMA_C 0.005f

#define BPM 37            // blocks per shape m
#define NPB 222           // points per block
#define GRID (MM * BPM)   // 296 = 2 CTAs/SM on 148 SMs -> all resident

typedef unsigned long long u64;

static __device__ __forceinline__ float ex2f(float x) {
    float y; asm("ex2.approx.f32 %0, %1;" : "=f"(y) : "f"(x)); return y;
}
static __device__ __forceinline__ float rcpf(float x) {
    float y; asm("rcp.approx.f32 %0, %1;" : "=f"(y) : "f"(x)); return y;
}
static __device__ __forceinline__ float rsqf(float x) {
    float y; asm("rsqrt.approx.f32 %0, %1;" : "=f"(y) : "f"(x)); return y;
}
static __device__ __forceinline__ u64 pk2(float lo, float hi) {
    u64 r; asm("mov.b64 %0, {%1, %2};" : "=l"(r)
               : "r"(__float_as_uint(lo)), "r"(__float_as_uint(hi)));
    return r;
}
static __device__ __forceinline__ void upk2(u64 v, float& lo, float& hi) {
    unsigned a, b; asm("mov.b64 {%0, %1}, %2;" : "=r"(a), "=r"(b) : "l"(v));
    lo = __uint_as_float(a); hi = __uint_as_float(b);
}
static __device__ __forceinline__ u64 fma2(u64 a, u64 b, u64 c) {
    u64 d; asm("fma.rn.f32x2 %0, %1, %2, %3;" : "=l"(d) : "l"(a), "l"(b), "l"(c)); return d;
}
static __device__ __forceinline__ u64 mul2(u64 a, u64 b) {
    u64 d; asm("mul.rn.f32x2 %0, %1, %2;" : "=l"(d) : "l"(a), "l"(b)); return d;
}
static __device__ __forceinline__ u64 add2(u64 a, u64 b) {
    u64 d; asm("add.rn.f32x2 %0, %1, %2;" : "=l"(d) : "l"(a), "l"(b)); return d;
}

// ------------- persistent device state (no allocations allowed) -------------
// 3 rotating moment buffers: [buf][quantity 0..4 = L,WTx,WTy,WTz,ST][m][k]
__device__ float gMom[3][5][MM][KK];
__device__ float gT0f[24];
__device__ float gBeta;

__device__ unsigned g_arrive = 0;
__device__ volatile unsigned g_phase = 0;

static __device__ __forceinline__ void grid_barrier() {
    __syncthreads();
    if (threadIdx.x == 0) {
        unsigned p = g_phase;
        __threadfence();
        unsigned rank = atomicAdd(&g_arrive, 1u);
        if (rank == GRID - 1) {
            g_arrive = 0;
            __threadfence();
            g_phase = p + 1;
        } else {
            while (g_phase == p) __nanosleep(32);
        }
        __threadfence();
    }
    __syncthreads();
}

#define ZTOT (5 * MM * KK)   // floats per moment buffer = 10240

// ------------------------------ fused kernel ---------------------------------
__global__ void __launch_bounds__(256, 2)
fused_kernel(const float* __restrict__ Vs,
             const float* __restrict__ X0,
             const float* __restrict__ Q0,
             float* __restrict__ out) {
    int bid = blockIdx.x, tid = threadIdx.x;
    int lane = tid & 31, warp = tid >> 5;

    // ----- shared: staged transformed points (duplicated pairs for f32x2) -----
    __shared__ float sTx[2 * NPB], sTy[2 * NPB], sTz[2 * NPB], shT[2 * NPB];
    __shared__ float s5[5][KK];
    // per-block replicated model state
    __shared__ float sC0[KK], sC1[KK], sDx[KK], sDy[KK], sDz[KK];
    __shared__ float sQ[KK], sX[3 * KK];
    __shared__ float sRm[72], sTm[24];          // current R (row-major), t per shape
    __shared__ float sRold[72], sTold[24];      // snapshot for solve
    __shared__ float sM[72], sTn[24];           // M = Rnew*Rold^T, new t
    __shared__ float smz[8], smx[24], smw[24], smp[72];
    __shared__ float sred[8];
    __shared__ float sBeta;

    // ------------------------------ init ------------------------------------
    // zero all 3 moment buffers (distributed across grid)
    for (int i = tid + bid * 256; i < 3 * ZTOT; i += GRID * 256)
        ((float*)gMom)[i] = 0.f;

    if (bid < 24) {
        int m = bid / 3, d = bid % 3;
        const float* src = Vs + (m * 3 + d) * NN;
        float s = 0.f;
        for (int n = tid; n < NN; n += 256) s += __ldg(src + n);
        #pragma unroll
        for (int o = 16; o; o >>= 1) s += __shfl_xor_sync(0xffffffffu, s, o);
        if (lane == 0) sred[warp] = s;
        __syncthreads();
        if (tid == 0) {
            float t = 0.f;
            for (int w = 0; w < 8; w++) t += sred[w];
            gT0f[bid] = -t / (float)NN;
        }
    } else if (bid == 24) {
        float q = __ldg(Q0 + tid);
        float s = q;
        #pragma unroll
        for (int o = 16; o; o >>= 1) s += __shfl_xor_sync(0xffffffffu, s, o);
        if (lane == 0) sred[warp] = s;
        __syncthreads();
        if (tid == 0) {
            float t = 0.f;
            for (int w = 0; w < 8; w++) t += sred[w];
            float mq = t / (float)KK;
            gBeta = GAMMA_C * mq * sqrtf(mq);
        }
    }
    grid_barrier();

    // ------------------------- per-block state setup --------------------------
    {
        int k = tid;
        float q = __ldg(Q0 + k);
        float x0 = __ldg(X0 + 3 * k), x1 = __ldg(X0 + 3 * k + 1), x2 = __ldg(X0 + 3 * k + 2);
        sQ[k] = q;
        sX[3 * k] = x0; sX[3 * k + 1] = x1; sX[3 * k + 2] = x2;
        float xs = x0 * x0 + x1 * x1 + x2 * x2;
        sC1[k] = -0.5f * q * LOG2E;
        sC0[k] = 1.5f * log2f(q) - 0.5f * q * xs * LOG2E;
        sDx[k] = q * LOG2E * x0;
        sDy[k] = q * LOG2E * x1;
        sDz[k] = q * LOG2E * x2;
    }
    if (tid < 72) sRm[tid] = ((tid % 9) % 4 == 0) ? 1.f : 0.f;
    if (tid < 24) sTm[tid] = __ldcg(&gT0f[tid]);
    if (tid == 0) sBeta = __ldcg(&gBeta);

    int m   = bid / BPM;
    int blk = bid % BPM;
    int n0 = blk * NPB;
    int count = min(NPB, NN - n0);
    const float* V0 = Vs + m * 3 * NN + n0;

    // zero-slice ownership for the rotating buffers
    int zper = (ZTOT + GRID - 1) / GRID;   // 35
    int zb = bid * zper;

    for (int it = 0; it < NUM_ITERS; it++) {
        int pc = it % 3;             // current buffer
        int pn = (it + 1) % 3;       // buffer to zero for next iter
        __syncthreads();             // state (sRm/sTm/consts) visible

        // ---- stage: transform points into T-space (duplicated pairs) ----
        if (tid < count) {
            float r0 = sRm[m * 9 + 0], r1 = sRm[m * 9 + 1], r2 = sRm[m * 9 + 2];
            float r3 = sRm[m * 9 + 3], r4 = sRm[m * 9 + 4], r5 = sRm[m * 9 + 5];
            float r6 = sRm[m * 9 + 6], r7 = sRm[m * 9 + 7], r8 = sRm[m * 9 + 8];
            float t0 = sTm[m * 3 + 0], t1 = sTm[m * 3 + 1], t2 = sTm[m * 3 + 2];
            float vx = __ldg(V0 + tid), vy = __ldg(V0 + NN + tid), vz = __ldg(V0 + 2 * NN + tid);
            float Tx = fmaf(r0, vx, fmaf(r1, vy, fmaf(r2, vz, t0)));
            float Ty = fmaf(r3, vx, fmaf(r4, vy, fmaf(r5, vz, t1)));
            float Tz = fmaf(r6, vx, fmaf(r7, vy, fmaf(r8, vz, t2)));
            float hT = fmaf(Tx, Tx, fmaf(Ty, Ty, Tz * Tz));
            sTx[2 * tid] = Tx; sTx[2 * tid + 1] = Tx;
            sTy[2 * tid] = Ty; sTy[2 * tid + 1] = Ty;
            sTz[2 * tid] = Tz; sTz[2 * tid + 1] = Tz;
            shT[2 * tid] = hT; shT[2 * tid + 1] = hT;
        }
        // zero this block's slice of NEXT buffer (safe: last read at solve_{it-2},
        // complete before B_{it-1}; next writes happen after B_it)
        {
            float* zn = (float*)gMom[pn];
            for (int j = tid; j < zper; j += 256)
                if (zb + j < ZTOT) zn[zb + j] = 0.f;
        }
        for (int i = tid; i < 5 * KK; i += 256) ((float*)s5)[i] = 0.f;

        // packed per-lane cluster constants: pair jj -> clusters (lane+64jj, +32)
        u64 C0p[4], C1p[4], DxP[4], DyP[4], DzP[4];
        #pragma unroll
        for (int jj = 0; jj < 4; jj++) {
            int ka = lane + 64 * jj, kb = ka + 32;
            C0p[jj] = pk2(sC0[ka], sC0[kb]);
            C1p[jj] = pk2(sC1[ka], sC1[kb]);
            DxP[jj] = pk2(sDx[ka], sDx[kb]);
            DyP[jj] = pk2(sDy[ka], sDy[kb]);
            DzP[jj] = pk2(sDz[ka], sDz[kb]);
        }
        float beta = sBeta;

        u64 aLp[4], aWxp[4], aWyp[4], aWzp[4], aSp[4];
        #pragma unroll
        for (int jj = 0; jj < 4; jj++) {
            aLp[jj] = 0ull; aWxp[jj] = 0ull; aWyp[jj] = 0ull; aWzp[jj] = 0ull; aSp[jj] = 0ull;
        }
        __syncthreads();

        int beg = warp * 28;
        int end = min(beg + 28, count);

        #pragma unroll 2
        for (int i = beg; i < end; i++) {
            u64 Txp = *(const u64*)&sTx[2 * i];
            u64 Typ = *(const u64*)&sTy[2 * i];
            u64 Tzp = *(const u64*)&sTz[2 * i];
            u64 hTp = *(const u64*)&shT[2 * i];

            float ap[8];
            #pragma unroll
            for (int jj = 0; jj < 4; jj++) {
                u64 arg = fma2(C1p[jj], hTp, C0p[jj]);
                arg = fma2(DxP[jj], Txp, arg);
                arg = fma2(DyP[jj], Typ, arg);
                arg = fma2(DzP[jj], Tzp, arg);
                float lo, hi; upk2(arg, lo, hi);
                ap[2 * jj]     = ex2f(lo);
                ap[2 * jj + 1] = ex2f(hi);
            }
            float ssum = ((ap[0] + ap[1]) + (ap[2] + ap[3]))
                       + ((ap[4] + ap[5]) + (ap[6] + ap[7]));
            #pragma unroll
            for (int o = 16; o; o >>= 1) ssum += __shfl_xor_sync(0xffffffffu, ssum, o);
            float inv = rcpf(ssum + beta);
            u64 invp = pk2(inv, inv);

            #pragma unroll
            for (int jj = 0; jj < 4; jj++) {
                u64 app = pk2(ap[2 * jj], ap[2 * jj + 1]);
                u64 a = mul2(app, invp);
                aLp[jj]  = add2(aLp[jj], a);
                aWxp[jj] = fma2(Txp, a, aWxp[jj]);
                aWyp[jj] = fma2(Typ, a, aWyp[jj]);
                aWzp[jj] = fma2(Tzp, a, aWzp[jj]);
                aSp[jj]  = fma2(hTp, a, aSp[jj]);
            }
        }

        // ---- block-level shared reduction, then global atomics ----
        #pragma unroll
        for (int jj = 0; jj < 4; jj++) {
            int ka = lane + 64 * jj, kb = ka + 32;
            float lo, hi;
            upk2(aLp[jj],  lo, hi); atomicAdd(&s5[0][ka], lo); atomicAdd(&s5[0][kb], hi);
            upk2(aWxp[jj], lo, hi); atomicAdd(&s5[1][ka], lo); atomicAdd(&s5[1][kb], hi);
            upk2(aWyp[jj], lo, hi); atomicAdd(&s5[2][ka], lo); atomicAdd(&s5[2][kb], hi);
            upk2(aWzp[jj], lo, hi); atomicAdd(&s5[3][ka], lo); atomicAdd(&s5[3][kb], hi);
            upk2(aSp[jj],  lo, hi); atomicAdd(&s5[4][ka], lo); atomicAdd(&s5[4][kb], hi);
        }
        __syncthreads();
        #pragma unroll
        for (int q = 0; q < 5; q++)
            atomicAdd(&gMom[pc][q][m][tid], s5[q][tid]);

        grid_barrier();

        // --------------------- solve (redundant, every block) -----------------
        // snapshot old R, t
        if (tid < 72) sRold[tid] = sRm[tid];
        if (tid < 24) sTold[tid] = sTm[tid];
        __syncthreads();

        // phase 1: warp == shape moment reduction (raw-space recovery)
        {
            int mm = warp;
            float Ro0 = sRold[mm*9+0], Ro1 = sRold[mm*9+1], Ro2 = sRold[mm*9+2];
            float Ro3 = sRold[mm*9+3], Ro4 = sRold[mm*9+4], Ro5 = sRold[mm*9+5];
            float Ro6 = sRold[mm*9+6], Ro7 = sRold[mm*9+7], Ro8 = sRold[mm*9+8];
            float tox = sTold[mm*3+0], toy = sTold[mm*3+1], toz = sTold[mm*3+2];
            float p[16];
            #pragma unroll
            for (int q = 0; q < 16; q++) p[q] = 0.f;
            #pragma unroll
            for (int j = 0; j < 8; j++) {
                int kk = lane + 32 * j;
                float L   = __ldcg(&gMom[pc][0][mm][kk]);
                float WTx = __ldcg(&gMom[pc][1][mm][kk]);
                float WTy = __ldcg(&gMom[pc][2][mm][kk]);
                float WTz = __ldcg(&gMom[pc][3][mm][kk]);
                float Q   = sQ[kk];
                float x0  = sX[3*kk], x1 = sX[3*kk+1], x2 = sX[3*kk+2];
                float WX = WTx - tox * L, WY = WTy - toy * L, WZ = WTz - toz * L;
                float wrx = Ro0 * WX + Ro3 * WY + Ro6 * WZ;   // Rold^T W
                float wry = Ro1 * WX + Ro4 * WY + Ro7 * WZ;
                float wrz = Ro2 * WX + Ro5 * WY + Ro8 * WZ;
                float b = L * Q;
                float wqx = wrx * Q, wqy = wry * Q, wqz = wrz * Q;
                p[0] += b;
                p[1] = fmaf(b, x0, p[1]);  p[2] = fmaf(b, x1, p[2]);  p[3] = fmaf(b, x2, p[3]);
                p[4] += wqx; p[5] += wqy; p[6] += wqz;
                p[7]  = fmaf(wqx, x0, p[7]);  p[8]  = fmaf(wqy, x0, p[8]);  p[9]  = fmaf(wqz, x0, p[9]);
                p[10] = fmaf(wqx, x1, p[10]); p[11] = fmaf(wqy, x1, p[11]); p[12] = fmaf(wqz, x1, p[12]);
                p[13] = fmaf(wqx, x2, p[13]); p[14] = fmaf(wqy, x2, p[14]); p[15] = fmaf(wqz, x2, p[15]);
            }
            #pragma unroll
            for (int q = 0; q < 16; q++) {
                float v = p[q];
                #pragma unroll
                for (int o = 16; o; o >>= 1) v += __shfl_xor_sync(0xffffffffu, v, o);
                p[q] = v;
            }
            if (lane == 0) {
                smz[mm] = p[0];
                smx[mm*3+0] = p[1]; smx[mm*3+1] = p[2]; smx[mm*3+2] = p[3];
                smw[mm*3+0] = p[4]; smw[mm*3+1] = p[5]; smw[mm*3+2] = p[6];
                #pragma unroll
                for (int q = 0; q < 9; q++) smp[mm*9+q] = p[7+q];
            }
        }
        __syncthreads();

        // 3x3 SVD per shape (8 threads, fp32 Jacobi)
        if (tid < MM) {
            int mm = tid;
            float z = smz[mm];
            float invz = 1.f / z;
            float mX[3], mW[3];
            for (int d = 0; d < 3; d++) { mX[d] = smx[mm*3+d]; mW[d] = smw[mm*3+d]; }
            float P[3][3];
            for (int e = 0; e < 3; e++)
                for (int d = 0; d < 3; d++)
                    P[e][d] = smp[mm*9 + e*3 + d] - mX[e] * mW[d] * invz;

            float A[3][3], V[3][3];
            for (int i = 0; i < 3; i++)
                for (int j = 0; j < 3; j++) {
                    A[i][j] = P[0][i]*P[0][j] + P[1][i]*P[1][j] + P[2][i]*P[2][j];
                    V[i][j] = (i == j) ? 1.f : 0.f;
                }
            #pragma unroll 1
            for (int sw = 0; sw < 8; sw++) {
                #pragma unroll
                for (int pi = 0; pi < 3; pi++) {
                    int p = (pi == 2) ? 1 : 0;
                    int q = (pi == 0) ? 1 : 2;
                    float apq = A[p][q];
                    if (fabsf(apq) > 1e-30f) {
                        float theta = (A[q][q] - A[p][p]) * 0.5f / apq;
                        float tt = ((theta >= 0.f) ? 1.f : -1.f) / (fabsf(theta) + sqrtf(fmaf(theta, theta, 1.f)));
                        float c = rsqf(fmaf(tt, tt, 1.f));
                        float s = tt * c;
                        int r = 3 - p - q;
                        float arp = A[r][p], arq = A[r][q];
                        A[p][p] -= tt * apq;
                        A[q][q] += tt * apq;
                        A[p][q] = 0.f; A[q][p] = 0.f;
                        float nrp = c * arp - s * arq, nrq = s * arp + c * arq;
                        A[r][p] = nrp; A[p][r] = nrp; A[r][q] = nrq; A[q][r] = nrq;
                        #pragma unroll
                        for (int rr = 0; rr < 3; rr++) {
                            float vp = V[rr][p], vq = V[rr][q];
                            V[rr][p] = c * vp - s * vq;
                            V[rr][q] = s * vp + c * vq;
                        }
                    }
                }
            }
            float ev[3] = { A[0][0], A[1][1], A[2][2] };
            #pragma unroll
            for (int pass = 0; pass < 3; pass++) {
                int i = (pass == 1) ? 1 : 0, j = i + 1;
                if (ev[j] > ev[i]) {
                    float te = ev[i]; ev[i] = ev[j]; ev[j] = te;
                    for (int r = 0; r < 3; r++) { float tv = V[r][i]; V[r][i] = V[r][j]; V[r][j] = tv; }
                }
            }
            float u[3][3];
            #pragma unroll
            for (int i = 0; i < 2; i++) {
                float sg2 = fmaxf(ev[i], 0.f);
                float inv = (sg2 > 1e-30f) ? rsqf(sg2) : 0.f;
                for (int e = 0; e < 3; e++)
                    u[i][e] = (P[e][0]*V[0][i] + P[e][1]*V[1][i] + P[e][2]*V[2][i]) * inv;
            }
            {
                float n0 = u[0][0]*u[0][0] + u[0][1]*u[0][1] + u[0][2]*u[0][2];
                float in0 = (n0 > 1e-30f) ? rsqf(n0) : 0.f;
                for (int e = 0; e < 3; e++) u[0][e] *= in0;
                float d01 = u[0][0]*u[1][0] + u[0][1]*u[1][1] + u[0][2]*u[1][2];
                for (int e = 0; e < 3; e++) u[1][e] -= d01 * u[0][e];
                float n1 = u[1][0]*u[1][0] + u[1][1]*u[1][1] + u[1][2]*u[1][2];
                float in1 = (n1 > 1e-30f) ? rsqf(n1) : 0.f;
                for (int e = 0; e < 3; e++) u[1][e] *= in1;
            }
            u[2][0] = u[0][1]*u[1][2] - u[0][2]*u[1][1];
            u[2][1] = u[0][2]*u[1][0] - u[0][0]*u[1][2];
            u[2][2] = u[0][0]*u[1][1] - u[0][1]*u[1][0];
            float detV = V[0][0]*(V[1][1]*V[2][2] - V[1][2]*V[2][1])
                       - V[0][1]*(V[1][0]*V[2][2] - V[1][2]*V[2][0])
                       + V[0][2]*(V[1][0]*V[2][1] - V[1][1]*V[2][0]);
            float dlt = (detV >= 0.f) ? 1.f : -1.f;

            float R[3][3];
            for (int a = 0; a < 3; a++)
                for (int b = 0; b < 3; b++)
                    R[a][b] = u[0][a]*V[b][0] + u[1][a]*V[b][1] + dlt*u[2][a]*V[b][2];
            float t[3];
            for (int a = 0; a < 3; a++)
                t[a] = (mX[a] - (R[a][0]*mW[0] + R[a][1]*mW[1] + R[a][2]*mW[2])) * invz;

            for (int a = 0; a < 3; a++) {
                for (int b = 0; b < 3; b++) {
                    sRm[mm*9 + a*3 + b] = R[a][b];
                    // M = Rnew * Rold^T
                    sM[mm*9 + a*3 + b] = R[a][0]*sRold[mm*9 + b*3 + 0]
                                       + R[a][1]*sRold[mm*9 + b*3 + 1]
                                       + R[a][2]*sRold[mm*9 + b*3 + 2];
                }
                sTm[mm*3 + a] = t[a];
                sTn[mm*3 + a] = t[a];
            }
        }
        __syncthreads();

        // epilogue: per-cluster X/Q update (thread == cluster), all in shared
        {
            int k = tid;
            float Xk0 = sX[3*k], Xk1 = sX[3*k+1], Xk2 = sX[3*k+2];
            float den = 0.f, Nx = 0.f, Ny = 0.f, Nz = 0.f, sA = 0.f;
            #pragma unroll
            for (int mm = 0; mm < MM; mm++) {
                float L   = __ldcg(&gMom[pc][0][mm][k]);
                float WTx = __ldcg(&gMom[pc][1][mm][k]);
                float WTy = __ldcg(&gMom[pc][2][mm][k]);
                float WTz = __ldcg(&gMom[pc][3][mm][k]);
                float ST  = __ldcg(&gMom[pc][4][mm][k]);
                float tox = sTold[mm*3+0], toy = sTold[mm*3+1], toz = sTold[mm*3+2];
                float tnx = sTn[mm*3+0],  tny = sTn[mm*3+1],  tnz = sTn[mm*3+2];
                float WX = WTx - tox * L, WY = WTy - toy * L, WZ = WTz - toz * L;
                float RWx = sM[mm*9+0]*WX + sM[mm*9+1]*WY + sM[mm*9+2]*WZ;
                float RWy = sM[mm*9+3]*WX + sM[mm*9+4]*WY + sM[mm*9+5]*WZ;
                float RWz = sM[mm*9+6]*WX + sM[mm*9+7]*WY + sM[mm*9+8]*WZ;
                float S2 = ST - 2.f*(tox*WTx + toy*WTy + toz*WTz)
                         + (tox*tox + toy*toy + toz*toz) * L;
                den += L;
                Nx += RWx + tnx * L;
                Ny += RWy + tny * L;
                Nz += RWz + tnz * L;
                sA += S2 + 2.f*(tnx*RWx + tny*RWy + tnz*RWz)
                    + (tnx*tnx + tny*tny + tnz*tnz) * L;
            }

            float Xn0, Xn1, Xn2;
            if (it > FIX_ITER) {
                float id = 1.f / den;
                Xn0 = Nx * id; Xn1 = Ny * id; Xn2 = Nz * id;
            } else {
                Xn0 = Xk0; Xn1 = Xk1; Xn2 = Xk2;
            }
            float xn2 = Xn0*Xn0 + Xn1*Xn1 + Xn2*Xn2;
            float wn = sA + xn2 * den - 2.f*(Xn0*Nx + Xn1*Ny + Xn2*Nz);
            float Qn = 3.f * den / (wn + 3.f * den * EPS_C);

            sX[3*k] = Xn0; sX[3*k+1] = Xn1; sX[3*k+2] = Xn2;
            sQ[k] = Qn;
            sC1[k] = -0.5f * Qn * LOG2E;
            sC0[k] = 1.5f * log2f(Qn) - 0.5f * Qn * xn2 * LOG2E;
            sDx[k] = Qn * LOG2E * Xn0;
            sDy[k] = Qn * LOG2E * Xn1;
            sDz[k] = Qn * LOG2E * Xn2;
        }
        // top-of-loop __syncthreads() separates epilogue writes from next stage
    }

    // ------------------------------ finalize ---------------------------------
    __syncthreads();
    {
        const int TOT = MM * 3 * NN;                  // 196608
        int per = (TOT + GRID - 1) / GRID;            // 665
        int s = bid * per, e = min(s + per, TOT);
        for (int idx = s + tid; idx < e; idx += 256) {
            int n = idx % NN;
            int md = idx / NN;
            int mq = md / 3;
            const float* Vm = Vs + mq * 3 * NN;
            float vx = __ldg(Vm + n), vy = __ldg(Vm + NN + n), vz = __ldg(Vm + 2 * NN + n);
            out[idx] = fmaf(sRm[3*md], vx, fmaf(sRm[3*md+1], vy, fmaf(sRm[3*md+2], vz, sTm[md])));
        }
        if (bid == 0) {
            if (tid < 72) out[196608 + tid] = sRm[tid];
            if (tid < 24) out[196680 + tid] = sTm[tid];
            for (int i = tid; i < 768; i += 256)
                out[196704 + i] = sX[i];
        }
    }
}

// ------------------------------ launch --------------------------------------
extern "C" void kernel_launch(void* const* d_in, const int* in_sizes, int n_in,
                              void* d_out, int out_size) {
    const float* Vs = (const float*)d_in[0];
    const float* X0 = (const float*)d_in[1];
    const float* Q0 = (const float*)d_in[2];
    float* out = (float*)d_out;

    fused_kernel<<<GRID, 256>>>(Vs, X0, Q0, out);
}

// round 10
// speedup vs baseline: 3.8252x; 1.0436x over previous
#include <cuda_runtime.h>
#include <math.h>

#define MM 8
#define NN 8192
#define KK 256
#define NUM_ITERS 6
#define FIX_ITER 1

#define LOG2E 1.44269504088896340736f
#define EPS_C 0.01f
#define GAMMA_C 0.005f

#define BPM 37            // blocks per shape m
#define NPB 222           // points per block
#define GRID (MM * BPM)   // 296 = 2 CTAs/SM on 148 SMs -> all resident

typedef unsigned long long u64;

static __device__ __forceinline__ float ex2f(float x) {
    float y; asm("ex2.approx.f32 %0, %1;" : "=f"(y) : "f"(x)); return y;
}
static __device__ __forceinline__ float rcpf(float x) {
    float y; asm("rcp.approx.f32 %0, %1;" : "=f"(y) : "f"(x)); return y;
}
static __device__ __forceinline__ float rsqf(float x) {
    float y; asm("rsqrt.approx.f32 %0, %1;" : "=f"(y) : "f"(x)); return y;
}
static __device__ __forceinline__ float lg2f(float x) {
    float y; asm("lg2.approx.f32 %0, %1;" : "=f"(y) : "f"(x)); return y;
}
static __device__ __forceinline__ u64 pk2(float lo, float hi) {
    u64 r; asm("mov.b64 %0, {%1, %2};" : "=l"(r)
               : "r"(__float_as_uint(lo)), "r"(__float_as_uint(hi)));
    return r;
}
static __device__ __forceinline__ void upk2(u64 v, float& lo, float& hi) {
    unsigned a, b; asm("mov.b64 {%0, %1}, %2;" : "=r"(a), "=r"(b) : "l"(v));
    lo = __uint_as_float(a); hi = __uint_as_float(b);
}
static __device__ __forceinline__ u64 fma2(u64 a, u64 b, u64 c) {
    u64 d; asm("fma.rn.f32x2 %0, %1, %2, %3;" : "=l"(d) : "l"(a), "l"(b), "l"(c)); return d;
}
static __device__ __forceinline__ u64 mul2(u64 a, u64 b) {
    u64 d; asm("mul.rn.f32x2 %0, %1, %2;" : "=l"(d) : "l"(a), "l"(b)); return d;
}
static __device__ __forceinline__ u64 add2(u64 a, u64 b) {
    u64 d; asm("add.rn.f32x2 %0, %1, %2;" : "=l"(d) : "l"(a), "l"(b)); return d;
}

// ------------- persistent device state (no allocations allowed) -------------
// 3 rotating moment buffers: [buf][quantity 0..4 = L,WTx,WTy,WTz,ST][m][k]
__device__ float gMom[3][5][MM][KK];
__device__ float gT0f[24];
__device__ float gBeta;

__device__ unsigned g_arrive = 0;
__device__ volatile unsigned g_phase = 0;

static __device__ __forceinline__ void grid_barrier() {
    __syncthreads();
    if (threadIdx.x == 0) {
        unsigned p = g_phase;
        __threadfence();
        unsigned rank = atomicAdd(&g_arrive, 1u);
        if (rank == GRID - 1) {
            g_arrive = 0;
            __threadfence();
            g_phase = p + 1;
        } else {
            while (g_phase == p) __nanosleep(32);
        }
        __threadfence();
    }
    __syncthreads();
}

#define ZTOT (5 * MM * KK)   // floats per moment buffer = 10240

// ------------------------------ fused kernel ---------------------------------
__global__ void __launch_bounds__(256, 2)
fused_kernel(const float* __restrict__ Vs,
             const float* __restrict__ X0,
             const float* __restrict__ Q0,
             float* __restrict__ out) {
    int bid = blockIdx.x, tid = threadIdx.x;
    int lane = tid & 31, warp = tid >> 5;

    // ----- shared: staged transformed points (duplicated pairs for f32x2) -----
    __shared__ float sTx[2 * NPB], sTy[2 * NPB], sTz[2 * NPB], shT[2 * NPB];
    __shared__ float s5[5][KK];
    // per-block replicated model state
    __shared__ float sC0[KK], sC1[KK], sDx[KK], sDy[KK], sDz[KK];
    __shared__ float sQ[KK], sX[3 * KK];
    __shared__ float sRm[72], sTm[24];          // current R (row-major), t per shape
    __shared__ float sRold[72], sTold[24];      // snapshot for solve
    __shared__ float sM[72], sTn[24];           // M = Rnew*Rold^T, new t
    __shared__ float smz[8], smx[24], smw[24], smp[72];
    __shared__ float sred[8];
    __shared__ float sBeta;

    // ------------------------------ init ------------------------------------
    // zero all 3 moment buffers (distributed across grid)
    for (int i = tid + bid * 256; i < 3 * ZTOT; i += GRID * 256)
        ((float*)gMom)[i] = 0.f;

    if (bid < 24) {
        int m = bid / 3, d = bid % 3;
        const float* src = Vs + (m * 3 + d) * NN;
        float s = 0.f;
        for (int n = tid; n < NN; n += 256) s += __ldg(src + n);
        #pragma unroll
        for (int o = 16; o; o >>= 1) s += __shfl_xor_sync(0xffffffffu, s, o);
        if (lane == 0) sred[warp] = s;
        __syncthreads();
        if (tid == 0) {
            float t = 0.f;
            for (int w = 0; w < 8; w++) t += sred[w];
            gT0f[bid] = -t / (float)NN;
        }
    } else if (bid == 24) {
        float q = __ldg(Q0 + tid);
        float s = q;
        #pragma unroll
        for (int o = 16; o; o >>= 1) s += __shfl_xor_sync(0xffffffffu, s, o);
        if (lane == 0) sred[warp] = s;
        __syncthreads();
        if (tid == 0) {
            float t = 0.f;
            for (int w = 0; w < 8; w++) t += sred[w];
            float mq = t / (float)KK;
            gBeta = GAMMA_C * mq * sqrtf(mq);
        }
    }
    grid_barrier();

    // ------------------------- per-block state setup --------------------------
    {
        int k = tid;
        float q = __ldg(Q0 + k);
        float x0 = __ldg(X0 + 3 * k), x1 = __ldg(X0 + 3 * k + 1), x2 = __ldg(X0 + 3 * k + 2);
        sQ[k] = q;
        sX[3 * k] = x0; sX[3 * k + 1] = x1; sX[3 * k + 2] = x2;
        float xs = x0 * x0 + x1 * x1 + x2 * x2;
        sC1[k] = -0.5f * q * LOG2E;
        sC0[k] = 1.5f * log2f(q) - 0.5f * q * xs * LOG2E;
        sDx[k] = q * LOG2E * x0;
        sDy[k] = q * LOG2E * x1;
        sDz[k] = q * LOG2E * x2;
    }
    if (tid < 72) sRm[tid] = ((tid % 9) % 4 == 0) ? 1.f : 0.f;
    if (tid < 24) sTm[tid] = __ldcg(&gT0f[tid]);
    if (tid == 0) sBeta = __ldcg(&gBeta);

    int m   = bid / BPM;
    int blk = bid % BPM;
    int n0 = blk * NPB;
    int count = min(NPB, NN - n0);
    const float* V0 = Vs + m * 3 * NN + n0;

    // zero-slice ownership for the rotating buffers
    int zper = (ZTOT + GRID - 1) / GRID;   // 35
    int zb = bid * zper;

    for (int it = 0; it < NUM_ITERS; it++) {
        int pc = it % 3;             // current buffer
        int pn = (it + 1) % 3;       // buffer to zero for next iter
        __syncthreads();             // state (sRm/sTm/consts) visible

        // ---- stage: transform points into T-space (duplicated pairs) ----
        if (tid < count) {
            float r0 = sRm[m * 9 + 0], r1 = sRm[m * 9 + 1], r2 = sRm[m * 9 + 2];
            float r3 = sRm[m * 9 + 3], r4 = sRm[m * 9 + 4], r5 = sRm[m * 9 + 5];
            float r6 = sRm[m * 9 + 6], r7 = sRm[m * 9 + 7], r8 = sRm[m * 9 + 8];
            float t0 = sTm[m * 3 + 0], t1 = sTm[m * 3 + 1], t2 = sTm[m * 3 + 2];
            float vx = __ldg(V0 + tid), vy = __ldg(V0 + NN + tid), vz = __ldg(V0 + 2 * NN + tid);
            float Tx = fmaf(r0, vx, fmaf(r1, vy, fmaf(r2, vz, t0)));
            float Ty = fmaf(r3, vx, fmaf(r4, vy, fmaf(r5, vz, t1)));
            float Tz = fmaf(r6, vx, fmaf(r7, vy, fmaf(r8, vz, t2)));
            float hT = fmaf(Tx, Tx, fmaf(Ty, Ty, Tz * Tz));
            sTx[2 * tid] = Tx; sTx[2 * tid + 1] = Tx;
            sTy[2 * tid] = Ty; sTy[2 * tid + 1] = Ty;
            sTz[2 * tid] = Tz; sTz[2 * tid + 1] = Tz;
            shT[2 * tid] = hT; shT[2 * tid + 1] = hT;
        }
        // zero this block's slice of NEXT buffer (safe: last read at solve_{it-2},
        // complete before B_{it-1}; next writes happen after B_it)
        {
            float* zn = (float*)gMom[pn];
            for (int j = tid; j < zper; j += 256)
                if (zb + j < ZTOT) zn[zb + j] = 0.f;
        }
        for (int i = tid; i < 5 * KK; i += 256) ((float*)s5)[i] = 0.f;

        // packed per-lane cluster constants: pair jj -> clusters (lane+64jj, +32)
        u64 C0p[4], C1p[4], DxP[4], DyP[4], DzP[4];
        #pragma unroll
        for (int jj = 0; jj < 4; jj++) {
            int ka = lane + 64 * jj, kb = ka + 32;
            C0p[jj] = pk2(sC0[ka], sC0[kb]);
            C1p[jj] = pk2(sC1[ka], sC1[kb]);
            DxP[jj] = pk2(sDx[ka], sDx[kb]);
            DyP[jj] = pk2(sDy[ka], sDy[kb]);
            DzP[jj] = pk2(sDz[ka], sDz[kb]);
        }
        float beta = sBeta;

        u64 aLp[4], aWxp[4], aWyp[4], aWzp[4], aSp[4];
        #pragma unroll
        for (int jj = 0; jj < 4; jj++) {
            aLp[jj] = 0ull; aWxp[jj] = 0ull; aWyp[jj] = 0ull; aWzp[jj] = 0ull; aSp[jj] = 0ull;
        }
        __syncthreads();

        int beg = warp * 28;
        int end = min(beg + 28, count);

        #pragma unroll 2
        for (int i = beg; i < end; i++) {
            u64 Txp = *(const u64*)&sTx[2 * i];
            u64 Typ = *(const u64*)&sTy[2 * i];
            u64 Tzp = *(const u64*)&sTz[2 * i];
            u64 hTp = *(const u64*)&shT[2 * i];

            u64 app[4];
            #pragma unroll
            for (int jj = 0; jj < 4; jj++) {
                u64 arg = fma2(C1p[jj], hTp, C0p[jj]);
                arg = fma2(DxP[jj], Txp, arg);
                arg = fma2(DyP[jj], Typ, arg);
                arg = fma2(DzP[jj], Tzp, arg);
                float lo, hi; upk2(arg, lo, hi);
                app[jj] = pk2(ex2f(lo), ex2f(hi));
            }
            // packed add-tree for the denominator, then shfl butterfly
            u64 s01 = add2(app[0], app[1]);
            u64 s23 = add2(app[2], app[3]);
            u64 stot = add2(s01, s23);
            float slo, shi; upk2(stot, slo, shi);
            float ssum = slo + shi;
            #pragma unroll
            for (int o = 16; o; o >>= 1) ssum += __shfl_xor_sync(0xffffffffu, ssum, o);
            float inv = rcpf(ssum + beta);
            u64 invp = pk2(inv, inv);

            #pragma unroll
            for (int jj = 0; jj < 4; jj++) {
                u64 a = mul2(app[jj], invp);
                aLp[jj]  = add2(aLp[jj], a);
                aWxp[jj] = fma2(Txp, a, aWxp[jj]);
                aWyp[jj] = fma2(Typ, a, aWyp[jj]);
                aWzp[jj] = fma2(Tzp, a, aWzp[jj]);
                aSp[jj]  = fma2(hTp, a, aSp[jj]);
            }
        }

        // ---- block-level shared reduction, then global atomics ----
        #pragma unroll
        for (int jj = 0; jj < 4; jj++) {
            int ka = lane + 64 * jj, kb = ka + 32;
            float lo, hi;
            upk2(aLp[jj],  lo, hi); atomicAdd(&s5[0][ka], lo); atomicAdd(&s5[0][kb], hi);
            upk2(aWxp[jj], lo, hi); atomicAdd(&s5[1][ka], lo); atomicAdd(&s5[1][kb], hi);
            upk2(aWyp[jj], lo, hi); atomicAdd(&s5[2][ka], lo); atomicAdd(&s5[2][kb], hi);
            upk2(aWzp[jj], lo, hi); atomicAdd(&s5[3][ka], lo); atomicAdd(&s5[3][kb], hi);
            upk2(aSp[jj],  lo, hi); atomicAdd(&s5[4][ka], lo); atomicAdd(&s5[4][kb], hi);
        }
        __syncthreads();
        #pragma unroll
        for (int q = 0; q < 5; q++)
            atomicAdd(&gMom[pc][q][m][tid], s5[q][tid]);

        grid_barrier();

        // --------------------- solve (redundant, every block) -----------------
        // snapshot old R, t
        if (tid < 72) sRold[tid] = sRm[tid];
        if (tid < 24) sTold[tid] = sTm[tid];
        __syncthreads();

        // phase 1: warp == shape moment reduction (raw-space recovery)
        {
            int mm = warp;
            float Ro0 = sRold[mm*9+0], Ro1 = sRold[mm*9+1], Ro2 = sRold[mm*9+2];
            float Ro3 = sRold[mm*9+3], Ro4 = sRold[mm*9+4], Ro5 = sRold[mm*9+5];
            float Ro6 = sRold[mm*9+6], Ro7 = sRold[mm*9+7], Ro8 = sRold[mm*9+8];
            float tox = sTold[mm*3+0], toy = sTold[mm*3+1], toz = sTold[mm*3+2];
            float p[16];
            #pragma unroll
            for (int q = 0; q < 16; q++) p[q] = 0.f;
            #pragma unroll
            for (int j = 0; j < 8; j++) {
                int kk = lane + 32 * j;
                float L   = __ldcg(&gMom[pc][0][mm][kk]);
                float WTx = __ldcg(&gMom[pc][1][mm][kk]);
                float WTy = __ldcg(&gMom[pc][2][mm][kk]);
                float WTz = __ldcg(&gMom[pc][3][mm][kk]);
                float Q   = sQ[kk];
                float x0  = sX[3*kk], x1 = sX[3*kk+1], x2 = sX[3*kk+2];
                float WX = WTx - tox * L, WY = WTy - toy * L, WZ = WTz - toz * L;
                float wrx = Ro0 * WX + Ro3 * WY + Ro6 * WZ;   // Rold^T W
                float wry = Ro1 * WX + Ro4 * WY + Ro7 * WZ;
                float wrz = Ro2 * WX + Ro5 * WY + Ro8 * WZ;
                float b = L * Q;
                float wqx = wrx * Q, wqy = wry * Q, wqz = wrz * Q;
                p[0] += b;
                p[1] = fmaf(b, x0, p[1]);  p[2] = fmaf(b, x1, p[2]);  p[3] = fmaf(b, x2, p[3]);
                p[4] += wqx; p[5] += wqy; p[6] += wqz;
                p[7]  = fmaf(wqx, x0, p[7]);  p[8]  = fmaf(wqy, x0, p[8]);  p[9]  = fmaf(wqz, x0, p[9]);
                p[10] = fmaf(wqx, x1, p[10]); p[11] = fmaf(wqy, x1, p[11]); p[12] = fmaf(wqz, x1, p[12]);
                p[13] = fmaf(wqx, x2, p[13]); p[14] = fmaf(wqy, x2, p[14]); p[15] = fmaf(wqz, x2, p[15]);
            }
            #pragma unroll
            for (int q = 0; q < 16; q++) {
                float v = p[q];
                #pragma unroll
                for (int o = 16; o; o >>= 1) v += __shfl_xor_sync(0xffffffffu, v, o);
                p[q] = v;
            }
            if (lane == 0) {
                smz[mm] = p[0];
                smx[mm*3+0] = p[1]; smx[mm*3+1] = p[2]; smx[mm*3+2] = p[3];
                smw[mm*3+0] = p[4]; smw[mm*3+1] = p[5]; smw[mm*3+2] = p[6];
                #pragma unroll
                for (int q = 0; q < 9; q++) smp[mm*9+q] = p[7+q];
            }
        }
        __syncthreads();

        // 3x3 SVD per shape (8 threads, fp32 Jacobi; IEEE sqrt for inf-safety)
        if (tid < MM) {
            int mm = tid;
            float z = smz[mm];
            float invz = rcpf(z);
            float mX[3], mW[3];
            for (int d = 0; d < 3; d++) { mX[d] = smx[mm*3+d]; mW[d] = smw[mm*3+d]; }
            float P[3][3];
            for (int e = 0; e < 3; e++)
                for (int d = 0; d < 3; d++)
                    P[e][d] = smp[mm*9 + e*3 + d] - mX[e] * mW[d] * invz;

            float A[3][3], V[3][3];
            for (int i = 0; i < 3; i++)
                for (int j = 0; j < 3; j++) {
                    A[i][j] = P[0][i]*P[0][j] + P[1][i]*P[1][j] + P[2][i]*P[2][j];
                    V[i][j] = (i == j) ? 1.f : 0.f;
                }
            #pragma unroll 1
            for (int sw = 0; sw < 6; sw++) {
                #pragma unroll
                for (int pi = 0; pi < 3; pi++) {
                    int p = (pi == 2) ? 1 : 0;
                    int q = (pi == 0) ? 1 : 2;
                    float apq = A[p][q];
                    if (fabsf(apq) > 1e-20f) {
                        float theta = (A[q][q] - A[p][p]) * 0.5f * rcpf(apq);
                        // sqrtf is inf-safe: theta=inf -> sqrt(inf)=inf -> rcpf(inf)=0 -> tt=0
                        float tt = ((theta >= 0.f) ? 1.f : -1.f)
                                 * rcpf(fabsf(theta) + sqrtf(fmaf(theta, theta, 1.f)));
                        float c = rsqf(fmaf(tt, tt, 1.f));
                        float s = tt * c;
                        int r = 3 - p - q;
                        float arp = A[r][p], arq = A[r][q];
                        A[p][p] -= tt * apq;
                        A[q][q] += tt * apq;
                        A[p][q] = 0.f; A[q][p] = 0.f;
                        float nrp = c * arp - s * arq, nrq = s * arp + c * arq;
                        A[r][p] = nrp; A[p][r] = nrp; A[r][q] = nrq; A[q][r] = nrq;
                        #pragma unroll
                        for (int rr = 0; rr < 3; rr++) {
                            float vp = V[rr][p], vq = V[rr][q];
                            V[rr][p] = c * vp - s * vq;
                            V[rr][q] = s * vp + c * vq;
                        }
                    }
                }
            }
            float ev[3] = { A[0][0], A[1][1], A[2][2] };
            #pragma unroll
            for (int pass = 0; pass < 3; pass++) {
                int i = (pass == 1) ? 1 : 0, j = i + 1;
                if (ev[j] > ev[i]) {
                    float te = ev[i]; ev[i] = ev[j]; ev[j] = te;
                    for (int r = 0; r < 3; r++) { float tv = V[r][i]; V[r][i] = V[r][j]; V[r][j] = tv; }
                }
            }
            float u[3][3];
            #pragma unroll
            for (int i = 0; i < 2; i++) {
                float sg2 = fmaxf(ev[i], 0.f);
                float inv = (sg2 > 1e-30f) ? rsqf(sg2) : 0.f;
                for (int e = 0; e < 3; e++)
                    u[i][e] = (P[e][0]*V[0][i] + P[e][1]*V[1][i] + P[e][2]*V[2][i]) * inv;
            }
            {
                float n0 = u[0][0]*u[0][0] + u[0][1]*u[0][1] + u[0][2]*u[0][2];
                float in0 = (n0 > 1e-30f) ? rsqf(n0) : 0.f;
                for (int e = 0; e < 3; e++) u[0][e] *= in0;
                float d01 = u[0][0]*u[1][0] + u[0][1]*u[1][1] + u[0][2]*u[1][2];
                for (int e = 0; e < 3; e++) u[1][e] -= d01 * u[0][e];
                float n1 = u[1][0]*u[1][0] + u[1][1]*u[1][1] + u[1][2]*u[1][2];
                float in1 = (n1 > 1e-30f) ? rsqf(n1) : 0.f;
                for (int e = 0; e < 3; e++) u[1][e] *= in1;
            }
            u[2][0] = u[0][1]*u[1][2] - u[0][2]*u[1][1];
            u[2][1] = u[0][2]*u[1][0] - u[0][0]*u[1][2];
            u[2][2] = u[0][0]*u[1][1] - u[0][1]*u[1][0];
            float detV = V[0][0]*(V[1][1]*V[2][2] - V[1][2]*V[2][1])
                       - V[0][1]*(V[1][0]*V[2][2] - V[1][2]*V[2][0])
                       + V[0][2]*(V[1][0]*V[2][1] - V[1][1]*V[2][0]);
            float dlt = (detV >= 0.f) ? 1.f : -1.f;

            float R[3][3];
            for (int a = 0; a < 3; a++)
                for (int b = 0; b < 3; b++)
                    R[a][b] = u[0][a]*V[b][0] + u[1][a]*V[b][1] + dlt*u[2][a]*V[b][2];
            float t[3];
            for (int a = 0; a < 3; a++)
                t[a] = (mX[a] - (R[a][0]*mW[0] + R[a][1]*mW[1] + R[a][2]*mW[2])) * invz;

            for (int a = 0; a < 3; a++) {
                for (int b = 0; b < 3; b++) {
                    sRm[mm*9 + a*3 + b] = R[a][b];
                    // M = Rnew * Rold^T
                    sM[mm*9 + a*3 + b] = R[a][0]*sRold[mm*9 + b*3 + 0]
                                       + R[a][1]*sRold[mm*9 + b*3 + 1]
                                       + R[a][2]*sRold[mm*9 + b*3 + 2];
                }
                sTm[mm*3 + a] = t[a];
                sTn[mm*3 + a] = t[a];
            }
        }
        __syncthreads();

        // epilogue: per-cluster X/Q update (thread == cluster), all in shared
        {
            int k = tid;
            float Xk0 = sX[3*k], Xk1 = sX[3*k+1], Xk2 = sX[3*k+2];
            float den = 0.f, Nx = 0.f, Ny = 0.f, Nz = 0.f, sA = 0.f;
            #pragma unroll
            for (int mm = 0; mm < MM; mm++) {
                float L   = __ldcg(&gMom[pc][0][mm][k]);
                float WTx = __ldcg(&gMom[pc][1][mm][k]);
                float WTy = __ldcg(&gMom[pc][2][mm][k]);
                float WTz = __ldcg(&gMom[pc][3][mm][k]);
                float ST  = __ldcg(&gMom[pc][4][mm][k]);
                float tox = sTold[mm*3+0], toy = sTold[mm*3+1], toz = sTold[mm*3+2];
                float tnx = sTn[mm*3+0],  tny = sTn[mm*3+1],  tnz = sTn[mm*3+2];
                float WX = WTx - tox * L, WY = WTy - toy * L, WZ = WTz - toz * L;
                float RWx = sM[mm*9+0]*WX + sM[mm*9+1]*WY + sM[mm*9+2]*WZ;
                float RWy = sM[mm*9+3]*WX + sM[mm*9+4]*WY + sM[mm*9+5]*WZ;
                float RWz = sM[mm*9+6]*WX + sM[mm*9+7]*WY + sM[mm*9+8]*WZ;
                float S2 = ST - 2.f*(tox*WTx + toy*WTy + toz*WTz)
                         + (tox*tox + toy*toy + toz*toz) * L;
                den += L;
                Nx += RWx + tnx * L;
                Ny += RWy + tny * L;
                Nz += RWz + tnz * L;
                sA += S2 + 2.f*(tnx*RWx + tny*RWy + tnz*RWz)
                    + (tnx*tnx + tny*tny + tnz*tnz) * L;
            }

            float Xn0, Xn1, Xn2;
            if (it > FIX_ITER) {
                float id = rcpf(den);
                Xn0 = Nx * id; Xn1 = Ny * id; Xn2 = Nz * id;
            } else {
                Xn0 = Xk0; Xn1 = Xk1; Xn2 = Xk2;
            }
            float xn2 = Xn0*Xn0 + Xn1*Xn1 + Xn2*Xn2;
            float wn = sA + xn2 * den - 2.f*(Xn0*Nx + Xn1*Ny + Xn2*Nz);
            float Qn = 3.f * den * rcpf(wn + 3.f * den * EPS_C);

            sX[3*k] = Xn0; sX[3*k+1] = Xn1; sX[3*k+2] = Xn2;
            sQ[k] = Qn;
            sC1[k] = -0.5f * Qn * LOG2E;
            sC0[k] = 1.5f * lg2f(Qn) - 0.5f * Qn * xn2 * LOG2E;
            sDx[k] = Qn * LOG2E * Xn0;
            sDy[k] = Qn * LOG2E * Xn1;
            sDz[k] = Qn * LOG2E * Xn2;
        }
        // top-of-loop __syncthreads() separates epilogue writes from next stage
    }

    // ------------------------------ finalize ---------------------------------
    __syncthreads();
    {
        const int TOT = MM * 3 * NN;                  // 196608
        int per = (TOT + GRID - 1) / GRID;            // 665
        int s = bid * per, e = min(s + per, TOT);
        for (int idx = s + tid; idx < e; idx += 256) {
            int n = idx % NN;
            int md = idx / NN;
            int mq = md / 3;
            const float* Vm = Vs + mq * 3 * NN;
            float vx = __ldg(Vm + n), vy = __ldg(Vm + NN + n), vz = __ldg(Vm + 2 * NN + n);
            out[idx] = fmaf(sRm[3*md], vx, fmaf(sRm[3*md+1], vy, fmaf(sRm[3*md+2], vz, sTm[md])));
        }
        if (bid == 0) {
            if (tid < 72) out[196608 + tid] = sRm[tid];
            if (tid < 24) out[196680 + tid] = sTm[tid];
            for (int i = tid; i < 768; i += 256)
                out[196704 + i] = sX[i];
        }
    }
}

// ------------------------------ launch --------------------------------------
extern "C" void kernel_launch(void* const* d_in, const int* in_sizes, int n_in,
                              void* d_out, int out_size) {
    const float* Vs = (const float*)d_in[0];
    const float* X0 = (const float*)d_in[1];
    const float* Q0 = (const float*)d_in[2];
    float* out = (float*)d_out;

    fused_kernel<<<GRID, 256>>>(Vs, X0, Q0, out);
}

// round 11
// speedup vs baseline: 3.8783x; 1.0139x over previous
#include <cuda_runtime.h>
#include <math.h>

#define MM 8
#define NN 8192
#define KK 256
#define NUM_ITERS 6
#define FIX_ITER 1

#define LOG2E 1.44269504088896340736f
#define EPS_C 0.01f
#define GAMMA_C 0.005f

#define BPM 37            // blocks per shape m
#define NPB 222           // points per block
#define GRID (MM * BPM)   // 296 = 2 CTAs/SM on 148 SMs -> all resident

typedef unsigned long long u64;

static __device__ __forceinline__ float ex2f(float x) {
    float y; asm("ex2.approx.f32 %0, %1;" : "=f"(y) : "f"(x)); return y;
}
static __device__ __forceinline__ float rcpf(float x) {
    float y; asm("rcp.approx.f32 %0, %1;" : "=f"(y) : "f"(x)); return y;
}
static __device__ __forceinline__ float rsqf(float x) {
    float y; asm("rsqrt.approx.f32 %0, %1;" : "=f"(y) : "f"(x)); return y;
}
static __device__ __forceinline__ float lg2f(float x) {
    float y; asm("lg2.approx.f32 %0, %1;" : "=f"(y) : "f"(x)); return y;
}
static __device__ __forceinline__ u64 pk2(float lo, float hi) {
    u64 r; asm("mov.b64 %0, {%1, %2};" : "=l"(r)
               : "r"(__float_as_uint(lo)), "r"(__float_as_uint(hi)));
    return r;
}
static __device__ __forceinline__ void upk2(u64 v, float& lo, float& hi) {
    unsigned a, b; asm("mov.b64 {%0, %1}, %2;" : "=r"(a), "=r"(b) : "l"(v));
    lo = __uint_as_float(a); hi = __uint_as_float(b);
}
static __device__ __forceinline__ u64 fma2(u64 a, u64 b, u64 c) {
    u64 d; asm("fma.rn.f32x2 %0, %1, %2, %3;" : "=l"(d) : "l"(a), "l"(b), "l"(c)); return d;
}
static __device__ __forceinline__ u64 mul2(u64 a, u64 b) {
    u64 d; asm("mul.rn.f32x2 %0, %1, %2;" : "=l"(d) : "l"(a), "l"(b)); return d;
}
static __device__ __forceinline__ u64 add2(u64 a, u64 b) {
    u64 d; asm("add.rn.f32x2 %0, %1, %2;" : "=l"(d) : "l"(a), "l"(b)); return d;
}

// ------------- persistent device state (no allocations allowed) -------------
// 3 rotating moment buffers: [buf][quantity 0..4 = L,WTx,WTy,WTz,ST][m][k]
__device__ float gMom[3][5][MM][KK];
__device__ float gT0f[24];
__device__ float gBeta;

__device__ unsigned g_arrive = 0;
__device__ volatile unsigned g_phase = 0;

static __device__ __forceinline__ void grid_barrier() {
    __syncthreads();
    if (threadIdx.x == 0) {
        unsigned p = g_phase;
        __threadfence();
        unsigned rank = atomicAdd(&g_arrive, 1u);
        if (rank == GRID - 1) {
            g_arrive = 0;
            __threadfence();
            g_phase = p + 1;
        } else {
            while (g_phase == p) __nanosleep(32);
        }
        __threadfence();
    }
    __syncthreads();
}

#define ZTOT (5 * MM * KK)   // floats per moment buffer = 10240

// ------------------------------ fused kernel ---------------------------------
__global__ void __launch_bounds__(256, 2)
fused_kernel(const float* __restrict__ Vs,
             const float* __restrict__ X0,
             const float* __restrict__ Q0,
             float* __restrict__ out) {
    int bid = blockIdx.x, tid = threadIdx.x;
    int lane = tid & 31, warp = tid >> 5;

    // ----- shared: staged transformed points (duplicated pairs for f32x2) -----
    __shared__ float sTx[2 * NPB], sTy[2 * NPB], sTz[2 * NPB], shT[2 * NPB];
    __shared__ float s5[5][KK];
    // per-block replicated model state
    __shared__ float sC0[KK], sC1[KK], sDx[KK], sDy[KK], sDz[KK];
    __shared__ float sQ[KK], sX[3 * KK];
    __shared__ float sRm[72], sTm[24];          // current R (row-major), t per shape
    __shared__ float sRold[72], sTold[24];      // snapshot for solve
    __shared__ float sM[72], sTn[24];           // M = Rnew*Rold^T, new t
    __shared__ float smz[8], smx[24], smw[24], smp[72];
    __shared__ float sred[8];
    __shared__ float sBeta;

    // ------------------------------ init ------------------------------------
    // zero all 3 moment buffers (distributed across grid)
    for (int i = tid + bid * 256; i < 3 * ZTOT; i += GRID * 256)
        ((float*)gMom)[i] = 0.f;

    if (bid < 24) {
        int m = bid / 3, d = bid % 3;
        const float* src = Vs + (m * 3 + d) * NN;
        float s = 0.f;
        for (int n = tid; n < NN; n += 256) s += __ldg(src + n);
        #pragma unroll
        for (int o = 16; o; o >>= 1) s += __shfl_xor_sync(0xffffffffu, s, o);
        if (lane == 0) sred[warp] = s;
        __syncthreads();
        if (tid == 0) {
            float t = 0.f;
            for (int w = 0; w < 8; w++) t += sred[w];
            gT0f[bid] = -t / (float)NN;
        }
    } else if (bid == 24) {
        float q = __ldg(Q0 + tid);
        float s = q;
        #pragma unroll
        for (int o = 16; o; o >>= 1) s += __shfl_xor_sync(0xffffffffu, s, o);
        if (lane == 0) sred[warp] = s;
        __syncthreads();
        if (tid == 0) {
            float t = 0.f;
            for (int w = 0; w < 8; w++) t += sred[w];
            float mq = t / (float)KK;
            gBeta = GAMMA_C * mq * sqrtf(mq);
        }
    }
    grid_barrier();

    // ------------------------- per-block state setup --------------------------
    {
        int k = tid;
        float q = __ldg(Q0 + k);
        float x0 = __ldg(X0 + 3 * k), x1 = __ldg(X0 + 3 * k + 1), x2 = __ldg(X0 + 3 * k + 2);
        sQ[k] = q;
        sX[3 * k] = x0; sX[3 * k + 1] = x1; sX[3 * k + 2] = x2;
        float xs = x0 * x0 + x1 * x1 + x2 * x2;
        sC1[k] = -0.5f * q * LOG2E;
        sC0[k] = 1.5f * log2f(q) - 0.5f * q * xs * LOG2E;
        sDx[k] = q * LOG2E * x0;
        sDy[k] = q * LOG2E * x1;
        sDz[k] = q * LOG2E * x2;
    }
    if (tid < 72) sRm[tid] = ((tid % 9) % 4 == 0) ? 1.f : 0.f;
    if (tid < 24) sTm[tid] = __ldcg(&gT0f[tid]);
    if (tid == 0) sBeta = __ldcg(&gBeta);

    int m   = bid / BPM;
    int blk = bid % BPM;
    int n0 = blk * NPB;
    int count = min(NPB, NN - n0);
    const float* V0 = Vs + m * 3 * NN + n0;

    // zero-slice ownership for the rotating buffers
    int zper = (ZTOT + GRID - 1) / GRID;   // 35
    int zb = bid * zper;

    for (int it = 0; it < NUM_ITERS; it++) {
        int pc = it % 3;             // current buffer
        int pn = (it + 1) % 3;       // buffer to zero for next iter
        __syncthreads();             // state (sRm/sTm/consts) visible

        // ---- stage: transform points into T-space (duplicated pairs) ----
        if (tid < count) {
            float r0 = sRm[m * 9 + 0], r1 = sRm[m * 9 + 1], r2 = sRm[m * 9 + 2];
            float r3 = sRm[m * 9 + 3], r4 = sRm[m * 9 + 4], r5 = sRm[m * 9 + 5];
            float r6 = sRm[m * 9 + 6], r7 = sRm[m * 9 + 7], r8 = sRm[m * 9 + 8];
            float t0 = sTm[m * 3 + 0], t1 = sTm[m * 3 + 1], t2 = sTm[m * 3 + 2];
            float vx = __ldg(V0 + tid), vy = __ldg(V0 + NN + tid), vz = __ldg(V0 + 2 * NN + tid);
            float Tx = fmaf(r0, vx, fmaf(r1, vy, fmaf(r2, vz, t0)));
            float Ty = fmaf(r3, vx, fmaf(r4, vy, fmaf(r5, vz, t1)));
            float Tz = fmaf(r6, vx, fmaf(r7, vy, fmaf(r8, vz, t2)));
            float hT = fmaf(Tx, Tx, fmaf(Ty, Ty, Tz * Tz));
            sTx[2 * tid] = Tx; sTx[2 * tid + 1] = Tx;
            sTy[2 * tid] = Ty; sTy[2 * tid + 1] = Ty;
            sTz[2 * tid] = Tz; sTz[2 * tid + 1] = Tz;
            shT[2 * tid] = hT; shT[2 * tid + 1] = hT;
        }
        // zero this block's slice of NEXT buffer (safe: last read at solve_{it-2},
        // complete before B_{it-1}; next writes happen after B_it)
        {
            float* zn = (float*)gMom[pn];
            for (int j = tid; j < zper; j += 256)
                if (zb + j < ZTOT) zn[zb + j] = 0.f;
        }
        for (int i = tid; i < 5 * KK; i += 256) ((float*)s5)[i] = 0.f;

        // fixed-point scale for integer warp reduction: warp-max of current Q
        {
            float qk = sQ[tid];
            #pragma unroll
            for (int o = 16; o; o >>= 1)
                qk = fmaxf(qk, __shfl_xor_sync(0xffffffffu, qk, o));
            if (lane == 0) sred[warp] = qk;
        }

        // packed per-lane cluster constants: pair jj -> clusters (lane+64jj, +32)
        u64 C0p[4], C1p[4], DxP[4], DyP[4], DzP[4];
        #pragma unroll
        for (int jj = 0; jj < 4; jj++) {
            int ka = lane + 64 * jj, kb = ka + 32;
            C0p[jj] = pk2(sC0[ka], sC0[kb]);
            C1p[jj] = pk2(sC1[ka], sC1[kb]);
            DxP[jj] = pk2(sDx[ka], sDx[kb]);
            DyP[jj] = pk2(sDy[ka], sDy[kb]);
            DzP[jj] = pk2(sDz[ka], sDz[kb]);
        }
        float beta = sBeta;

        u64 aLp[4], aWxp[4], aWyp[4], aWzp[4], aSp[4];
        #pragma unroll
        for (int jj = 0; jj < 4; jj++) {
            aLp[jj] = 0ull; aWxp[jj] = 0ull; aWyp[jj] = 0ull; aWzp[jj] = 0ull; aSp[jj] = 0ull;
        }
        __syncthreads();

        // every thread computes the identical scale deterministically
        float scalef, invscalef;
        {
            float qmax = sred[0];
            #pragma unroll
            for (int w = 1; w < 8; w++) qmax = fmaxf(qmax, sred[w]);
            float mq15 = qmax * sqrtf(qmax);           // max ap value bound
            float l = ceilf(lg2f(256.f * mq15));       // denominator bound = 2^l
            scalef    = ex2f(29.f - l);                // sum*scale <= 2^29
            invscalef = ex2f(l - 29.f);
        }

        int beg = warp * 28;
        int end = min(beg + 28, count);

        #pragma unroll 2
        for (int i = beg; i < end; i++) {
            u64 Txp = *(const u64*)&sTx[2 * i];
            u64 Typ = *(const u64*)&sTy[2 * i];
            u64 Tzp = *(const u64*)&sTz[2 * i];
            u64 hTp = *(const u64*)&shT[2 * i];

            u64 app[4];
            #pragma unroll
            for (int jj = 0; jj < 4; jj++) {
                u64 arg = fma2(C1p[jj], hTp, C0p[jj]);
                arg = fma2(DxP[jj], Txp, arg);
                arg = fma2(DyP[jj], Typ, arg);
                arg = fma2(DzP[jj], Tzp, arg);
                float lo, hi; upk2(arg, lo, hi);
                app[jj] = pk2(ex2f(lo), ex2f(hi));
            }
            // packed add-tree, then ONE integer HW warp reduction (fixed point)
            u64 s01 = add2(app[0], app[1]);
            u64 s23 = add2(app[2], app[3]);
            u64 stot = add2(s01, s23);
            float slo, shi; upk2(stot, slo, shi);
            unsigned pi = __float2uint_rn((slo + shi) * scalef);
            unsigned si = __reduce_add_sync(0xffffffffu, pi);
            float inv = rcpf(fmaf(__uint2float_rn(si), invscalef, beta));
            u64 invp = pk2(inv, inv);

            #pragma unroll
            for (int jj = 0; jj < 4; jj++) {
                u64 a = mul2(app[jj], invp);
                aLp[jj]  = add2(aLp[jj], a);
                aWxp[jj] = fma2(Txp, a, aWxp[jj]);
                aWyp[jj] = fma2(Typ, a, aWyp[jj]);
                aWzp[jj] = fma2(Tzp, a, aWzp[jj]);
                aSp[jj]  = fma2(hTp, a, aSp[jj]);
            }
        }

        // ---- block-level shared reduction, then global atomics ----
        #pragma unroll
        for (int jj = 0; jj < 4; jj++) {
            int ka = lane + 64 * jj, kb = ka + 32;
            float lo, hi;
            upk2(aLp[jj],  lo, hi); atomicAdd(&s5[0][ka], lo); atomicAdd(&s5[0][kb], hi);
            upk2(aWxp[jj], lo, hi); atomicAdd(&s5[1][ka], lo); atomicAdd(&s5[1][kb], hi);
            upk2(aWyp[jj], lo, hi); atomicAdd(&s5[2][ka], lo); atomicAdd(&s5[2][kb], hi);
            upk2(aWzp[jj], lo, hi); atomicAdd(&s5[3][ka], lo); atomicAdd(&s5[3][kb], hi);
            upk2(aSp[jj],  lo, hi); atomicAdd(&s5[4][ka], lo); atomicAdd(&s5[4][kb], hi);
        }
        __syncthreads();
        #pragma unroll
        for (int q = 0; q < 5; q++)
            atomicAdd(&gMom[pc][q][m][tid], s5[q][tid]);

        grid_barrier();

        // --------------------- solve (redundant, every block) -----------------
        // snapshot old R, t
        if (tid < 72) sRold[tid] = sRm[tid];
        if (tid < 24) sTold[tid] = sTm[tid];
        __syncthreads();

        // phase 1: warp == shape moment reduction (raw-space recovery)
        {
            int mm = warp;
            float Ro0 = sRold[mm*9+0], Ro1 = sRold[mm*9+1], Ro2 = sRold[mm*9+2];
            float Ro3 = sRold[mm*9+3], Ro4 = sRold[mm*9+4], Ro5 = sRold[mm*9+5];
            float Ro6 = sRold[mm*9+6], Ro7 = sRold[mm*9+7], Ro8 = sRold[mm*9+8];
            float tox = sTold[mm*3+0], toy = sTold[mm*3+1], toz = sTold[mm*3+2];
            float p[16];
            #pragma unroll
            for (int q = 0; q < 16; q++) p[q] = 0.f;
            #pragma unroll
            for (int j = 0; j < 8; j++) {
                int kk = lane + 32 * j;
                float L   = __ldcg(&gMom[pc][0][mm][kk]);
                float WTx = __ldcg(&gMom[pc][1][mm][kk]);
                float WTy = __ldcg(&gMom[pc][2][mm][kk]);
                float WTz = __ldcg(&gMom[pc][3][mm][kk]);
                float Q   = sQ[kk];
                float x0  = sX[3*kk], x1 = sX[3*kk+1], x2 = sX[3*kk+2];
                float WX = WTx - tox * L, WY = WTy - toy * L, WZ = WTz - toz * L;
                float wrx = Ro0 * WX + Ro3 * WY + Ro6 * WZ;   // Rold^T W
                float wry = Ro1 * WX + Ro4 * WY + Ro7 * WZ;
                float wrz = Ro2 * WX + Ro5 * WY + Ro8 * WZ;
                float b = L * Q;
                float wqx = wrx * Q, wqy = wry * Q, wqz = wrz * Q;
                p[0] += b;
                p[1] = fmaf(b, x0, p[1]);  p[2] = fmaf(b, x1, p[2]);  p[3] = fmaf(b, x2, p[3]);
                p[4] += wqx; p[5] += wqy; p[6] += wqz;
                p[7]  = fmaf(wqx, x0, p[7]);  p[8]  = fmaf(wqy, x0, p[8]);  p[9]  = fmaf(wqz, x0, p[9]);
                p[10] = fmaf(wqx, x1, p[10]); p[11] = fmaf(wqy, x1, p[11]); p[12] = fmaf(wqz, x1, p[12]);
                p[13] = fmaf(wqx, x2, p[13]); p[14] = fmaf(wqy, x2, p[14]); p[15] = fmaf(wqz, x2, p[15]);
            }
            #pragma unroll
            for (int q = 0; q < 16; q++) {
                float v = p[q];
                #pragma unroll
                for (int o = 16; o; o >>= 1) v += __shfl_xor_sync(0xffffffffu, v, o);
                p[q] = v;
            }
            if (lane == 0) {
                smz[mm] = p[0];
                smx[mm*3+0] = p[1]; smx[mm*3+1] = p[2]; smx[mm*3+2] = p[3];
                smw[mm*3+0] = p[4]; smw[mm*3+1] = p[5]; smw[mm*3+2] = p[6];
                #pragma unroll
                for (int q = 0; q < 9; q++) smp[mm*9+q] = p[7+q];
            }
        }
        __syncthreads();

        // 3x3 SVD per shape (8 threads, fp32 Jacobi; IEEE sqrt for inf-safety)
        if (tid < MM) {
            int mm = tid;
            float z = smz[mm];
            float invz = rcpf(z);
            float mX[3], mW[3];
            for (int d = 0; d < 3; d++) { mX[d] = smx[mm*3+d]; mW[d] = smw[mm*3+d]; }
            float P[3][3];
            for (int e = 0; e < 3; e++)
                for (int d = 0; d < 3; d++)
                    P[e][d] = smp[mm*9 + e*3 + d] - mX[e] * mW[d] * invz;

            float A[3][3], V[3][3];
            for (int i = 0; i < 3; i++)
                for (int j = 0; j < 3; j++) {
                    A[i][j] = P[0][i]*P[0][j] + P[1][i]*P[1][j] + P[2][i]*P[2][j];
                    V[i][j] = (i == j) ? 1.f : 0.f;
                }
            #pragma unroll 1
            for (int sw = 0; sw < 6; sw++) {
                #pragma unroll
                for (int pi = 0; pi < 3; pi++) {
                    int p = (pi == 2) ? 1 : 0;
                    int q = (pi == 0) ? 1 : 2;
                    float apq = A[p][q];
                    if (fabsf(apq) > 1e-20f) {
                        float theta = (A[q][q] - A[p][p]) * 0.5f * rcpf(apq);
                        // sqrtf is inf-safe: theta=inf -> sqrt(inf)=inf -> rcpf(inf)=0 -> tt=0
                        float tt = ((theta >= 0.f) ? 1.f : -1.f)
                                 * rcpf(fabsf(theta) + sqrtf(fmaf(theta, theta, 1.f)));
                        float c = rsqf(fmaf(tt, tt, 1.f));
                        float s = tt * c;
                        int r = 3 - p - q;
                        float arp = A[r][p], arq = A[r][q];
                        A[p][p] -= tt * apq;
                        A[q][q] += tt * apq;
                        A[p][q] = 0.f; A[q][p] = 0.f;
                        float nrp = c * arp - s * arq, nrq = s * arp + c * arq;
                        A[r][p] = nrp; A[p][r] = nrp; A[r][q] = nrq; A[q][r] = nrq;
                        #pragma unroll
                        for (int rr = 0; rr < 3; rr++) {
                            float vp = V[rr][p], vq = V[rr][q];
                            V[rr][p] = c * vp - s * vq;
                            V[rr][q] = s * vp + c * vq;
                        }
                    }
                }
            }
            float ev[3] = { A[0][0], A[1][1], A[2][2] };
            #pragma unroll
            for (int pass = 0; pass < 3; pass++) {
                int i = (pass == 1) ? 1 : 0, j = i + 1;
                if (ev[j] > ev[i]) {
                    float te = ev[i]; ev[i] = ev[j]; ev[j] = te;
                    for (int r = 0; r < 3; r++) { float tv = V[r][i]; V[r][i] = V[r][j]; V[r][j] = tv; }
                }
            }
            float u[3][3];
            #pragma unroll
            for (int i = 0; i < 2; i++) {
                float sg2 = fmaxf(ev[i], 0.f);
                float inv = (sg2 > 1e-30f) ? rsqf(sg2) : 0.f;
                for (int e = 0; e < 3; e++)
                    u[i][e] = (P[e][0]*V[0][i] + P[e][1]*V[1][i] + P[e][2]*V[2][i]) * inv;
            }
            {
                float n0 = u[0][0]*u[0][0] + u[0][1]*u[0][1] + u[0][2]*u[0][2];
                float in0 = (n0 > 1e-30f) ? rsqf(n0) : 0.f;
                for (int e = 0; e < 3; e++) u[0][e] *= in0;
                float d01 = u[0][0]*u[1][0] + u[0][1]*u[1][1] + u[0][2]*u[1][2];
                for (int e = 0; e < 3; e++) u[1][e] -= d01 * u[0][e];
                float n1 = u[1][0]*u[1][0] + u[1][1]*u[1][1] + u[1][2]*u[1][2];
                float in1 = (n1 > 1e-30f) ? rsqf(n1) : 0.f;
                for (int e = 0; e < 3; e++) u[1][e] *= in1;
            }
            u[2][0] = u[0][1]*u[1][2] - u[0][2]*u[1][1];
            u[2][1] = u[0][2]*u[1][0] - u[0][0]*u[1][2];
            u[2][2] = u[0][0]*u[1][1] - u[0][1]*u[1][0];
            float detV = V[0][0]*(V[1][1]*V[2][2] - V[1][2]*V[2][1])
                       - V[0][1]*(V[1][0]*V[2][2] - V[1][2]*V[2][0])
                       + V[0][2]*(V[1][0]*V[2][1] - V[1][1]*V[2][0]);
            float dlt = (detV >= 0.f) ? 1.f : -1.f;

            float R[3][3];
            for (int a = 0; a < 3; a++)
                for (int b = 0; b < 3; b++)
                    R[a][b] = u[0][a]*V[b][0] + u[1][a]*V[b][1] + dlt*u[2][a]*V[b][2];
            float t[3];
            for (int a = 0; a < 3; a++)
                t[a] = (mX[a] - (R[a][0]*mW[0] + R[a][1]*mW[1] + R[a][2]*mW[2])) * invz;

            for (int a = 0; a < 3; a++) {
                for (int b = 0; b < 3; b++) {
                    sRm[mm*9 + a*3 + b] = R[a][b];
                    // M = Rnew * Rold^T
                    sM[mm*9 + a*3 + b] = R[a][0]*sRold[mm*9 + b*3 + 0]
                                       + R[a][1]*sRold[mm*9 + b*3 + 1]
                                       + R[a][2]*sRold[mm*9 + b*3 + 2];
                }
                sTm[mm*3 + a] = t[a];
                sTn[mm*3 + a] = t[a];
            }
        }
        __syncthreads();

        // epilogue: per-cluster X/Q update (thread == cluster), all in shared
        {
            int k = tid;
            float Xk0 = sX[3*k], Xk1 = sX[3*k+1], Xk2 = sX[3*k+2];
            float den = 0.f, Nx = 0.f, Ny = 0.f, Nz = 0.f, sA = 0.f;
            #pragma unroll
            for (int mm = 0; mm < MM; mm++) {
                float L   = __ldcg(&gMom[pc][0][mm][k]);
                float WTx = __ldcg(&gMom[pc][1][mm][k]);
                float WTy = __ldcg(&gMom[pc][2][mm][k]);
                float WTz = __ldcg(&gMom[pc][3][mm][k]);
                float ST  = __ldcg(&gMom[pc][4][mm][k]);
                float tox = sTold[mm*3+0], toy = sTold[mm*3+1], toz = sTold[mm*3+2];
                float tnx = sTn[mm*3+0],  tny = sTn[mm*3+1],  tnz = sTn[mm*3+2];
                float WX = WTx - tox * L, WY = WTy - toy * L, WZ = WTz - toz * L;
                float RWx = sM[mm*9+0]*WX + sM[mm*9+1]*WY + sM[mm*9+2]*WZ;
                float RWy = sM[mm*9+3]*WX + sM[mm*9+4]*WY + sM[mm*9+5]*WZ;
                float RWz = sM[mm*9+6]*WX + sM[mm*9+7]*WY + sM[mm*9+8]*WZ;
                float S2 = ST - 2.f*(tox*WTx + toy*WTy + toz*WTz)
                         + (tox*tox + toy*toy + toz*toz) * L;
                den += L;
                Nx += RWx + tnx * L;
                Ny += RWy + tny * L;
                Nz += RWz + tnz * L;
                sA += S2 + 2.f*(tnx*RWx + tny*RWy + tnz*RWz)
                    + (tnx*tnx + tny*tny + tnz*tnz) * L;
            }

            float Xn0, Xn1, Xn2;
            if (it > FIX_ITER) {
                float id = rcpf(den);
                Xn0 = Nx * id; Xn1 = Ny * id; Xn2 = Nz * id;
            } else {
                Xn0 = Xk0; Xn1 = Xk1; Xn2 = Xk2;
            }
            float xn2 = Xn0*Xn0 + Xn1*Xn1 + Xn2*Xn2;
            float wn = sA + xn2 * den - 2.f*(Xn0*Nx + Xn1*Ny + Xn2*Nz);
            float Qn = 3.f * den * rcpf(wn + 3.f * den * EPS_C);

            sX[3*k] = Xn0; sX[3*k+1] = Xn1; sX[3*k+2] = Xn2;
            sQ[k] = Qn;
            sC1[k] = -0.5f * Qn * LOG2E;
            sC0[k] = 1.5f * lg2f(Qn) - 0.5f * Qn * xn2 * LOG2E;
            sDx[k] = Qn * LOG2E * Xn0;
            sDy[k] = Qn * LOG2E * Xn1;
            sDz[k] = Qn * LOG2E * Xn2;
        }
        // top-of-loop __syncthreads() separates epilogue writes from next stage
    }

    // ------------------------------ finalize ---------------------------------
    __syncthreads();
    {
        const int TOT = MM * 3 * NN;                  // 196608
        int per = (TOT + GRID - 1) / GRID;            // 665
        int s = bid * per, e = min(s + per, TOT);
        for (int idx = s + tid; idx < e; idx += 256) {
            int n = idx % NN;
            int md = idx / NN;
            int mq = md / 3;
            const float* Vm = Vs + mq * 3 * NN;
            float vx = __ldg(Vm + n), vy = __ldg(Vm + NN + n), vz = __ldg(Vm + 2 * NN + n);
            out[idx] = fmaf(sRm[3*md], vx, fmaf(sRm[3*md+1], vy, fmaf(sRm[3*md+2], vz, sTm[md])));
        }
        if (bid == 0) {
            if (tid < 72) out[196608 + tid] = sRm[tid];
            if (tid < 24) out[196680 + tid] = sTm[tid];
            for (int i = tid; i < 768; i += 256)
                out[196704 + i] = sX[i];
        }
    }
}

// ------------------------------ launch --------------------------------------
extern "C" void kernel_launch(void* const* d_in, const int* in_sizes, int n_in,
                              void* d_out, int out_size) {
    const float* Vs = (const float*)d_in[0];
    const float* X0 = (const float*)d_in[1];
    const float* Q0 = (const float*)d_in[2];
    float* out = (float*)d_out;

    fused_kernel<<<GRID, 256>>>(Vs, X0, Q0, out);
}